// round 13
// baseline (speedup 1.0000x reference)
#include <cuda_runtime.h>
#include <cuda_fp16.h>
#include <math.h>
#include <stdint.h>

#define EPSF 1e-5f

// ---------------- scratch ----------------
__device__ int8_t g_xq[4194304];     // quantized x int8 [4096,1024]
__device__ int8_t g_cq[4194304];     // quantized context int8
__device__ int8_t g_aq[4194304];     // quantized attn-out int8
__device__ int8_t g_wt[4][1048576];  // ternary weights int8 (q,k,v,o)
__device__ float  g_xscale[4096];
__device__ float  g_cscale[4096];
__device__ float  g_ascale[4096];
__device__ __half g_qh[4194304];     // Q hi fp16 (pre-scaled by 0.125)
__device__ __half g_ql[4194304];     // Q lo
__device__ __half g_kh[4194304];     // K hi
__device__ __half g_kl[4194304];     // K lo
__device__ __half g_vh[4194304];     // V hi
__device__ __half g_vl[4194304];     // V lo
__device__ float  g_attn[4194304];   // attention output fp32
__device__ double g_wpart[256];
__device__ float  g_wcm[4];
__device__ float  g_wscale[4];

// ---------------- ldmatrix helpers ----------------
__device__ __forceinline__ void ldsm4(uint32_t* r, const void* p)
{
    uint32_t a = (uint32_t)__cvta_generic_to_shared(p);
    asm volatile("ldmatrix.sync.aligned.m8n8.x4.shared.b16 {%0,%1,%2,%3}, [%4];"
                 : "=r"(r[0]), "=r"(r[1]), "=r"(r[2]), "=r"(r[3]) : "r"(a));
}

__device__ __forceinline__ void ldsm4t(uint32_t* r, const void* p)
{
    uint32_t a = (uint32_t)__cvta_generic_to_shared(p);
    asm volatile("ldmatrix.sync.aligned.m8n8.x4.trans.shared.b16 {%0,%1,%2,%3}, [%4];"
                 : "=r"(r[0]), "=r"(r[1]), "=r"(r[2]), "=r"(r[3]) : "r"(a));
}

// ---------------- weight |w| sum (double accumulation, deterministic) ----------------
__global__ __launch_bounds__(256) void wsum_kernel(const float* __restrict__ w0,
                                                   const float* __restrict__ w1,
                                                   const float* __restrict__ w2,
                                                   const float* __restrict__ w3)
{
    const float* w = (blockIdx.y == 0) ? w0 : (blockIdx.y == 1) ? w1 : (blockIdx.y == 2) ? w2 : w3;
    int base = blockIdx.x * 16384;
    int t = threadIdx.x;
    double s = 0.0;
    #pragma unroll
    for (int i = 0; i < 16; i++) {
        float4 v = *(const float4*)(w + base + i * 1024 + t * 4);
        s += (double)fabsf(v.x) + (double)fabsf(v.y) + (double)fabsf(v.z) + (double)fabsf(v.w);
    }
    #pragma unroll
    for (int o = 16; o > 0; o >>= 1) s += __shfl_down_sync(0xffffffffu, s, o);
    __shared__ double ws[8];
    if ((t & 31) == 0) ws[t >> 5] = s;
    __syncthreads();
    if (t == 0) {
        double tot = 0.0;
        #pragma unroll
        for (int i = 0; i < 8; i++) tot += ws[i];
        g_wpart[blockIdx.y * 64 + blockIdx.x] = tot;
    }
}

// wquant with fused scale computation (each block recomputes the deterministic mean)
__global__ __launch_bounds__(256) void wquant_kernel(const float* __restrict__ w0,
                                                     const float* __restrict__ w1,
                                                     const float* __restrict__ w2,
                                                     const float* __restrict__ w3)
{
    int m = blockIdx.y;
    const float* w = (m == 0) ? w0 : (m == 1) ? w1 : (m == 2) ? w2 : w3;
    __shared__ float sh_s;
    if (threadIdx.x == 0) {
        double tot = 0.0;
        #pragma unroll 8
        for (int i = 0; i < 64; i++) tot += g_wpart[m * 64 + i];
        float mean = (float)(tot / 1048576.0);
        float cm = fmaxf(mean, EPSF);
        sh_s = 1.0f / cm;
        if (blockIdx.x == 0) {
            g_wcm[m] = cm;
            g_wscale[m] = 1.0f / cm;
        }
    }
    __syncthreads();
    float s = sh_s;
    int idx = (blockIdx.x * 256 + threadIdx.x) * 4;
    float4 v = *(const float4*)(w + idx);
    char4 o;
    o.x = (char)fminf(fmaxf(rintf(v.x * s), -1.f), 1.f);
    o.y = (char)fminf(fmaxf(rintf(v.y * s), -1.f), 1.f);
    o.z = (char)fminf(fmaxf(rintf(v.z * s), -1.f), 1.f);
    o.w = (char)fminf(fmaxf(rintf(v.w * s), -1.f), 1.f);
    *(char4*)(g_wt[m] + idx) = o;
}

// ---------------- per-token int8 absmax quant (fused x+ctx via grid.y) ----------------
__global__ __launch_bounds__(256) void act_quant2_i8(const float* __restrict__ in0,
                                                     const float* __restrict__ in1,
                                                     int8_t* __restrict__ out0,
                                                     int8_t* __restrict__ out1,
                                                     float* __restrict__ rs0,
                                                     float* __restrict__ rs1)
{
    const float* in = blockIdx.y ? in1 : in0;
    int8_t* out = blockIdx.y ? out1 : out0;
    float* rowscale = blockIdx.y ? rs1 : rs0;
    int row = blockIdx.x;
    int t = threadIdx.x;
    const float4* ri = (const float4*)(in + (size_t)row * 1024);
    float4 v = ri[t];
    float am = fmaxf(fmaxf(fabsf(v.x), fabsf(v.y)), fmaxf(fabsf(v.z), fabsf(v.w)));
    #pragma unroll
    for (int o = 16; o > 0; o >>= 1) am = fmaxf(am, __shfl_xor_sync(0xffffffffu, am, o));
    __shared__ float wm[8];
    if ((t & 31) == 0) wm[t >> 5] = am;
    __syncthreads();
    am = wm[0];
    #pragma unroll
    for (int i = 1; i < 8; i++) am = fmaxf(am, wm[i]);
    float amax = fmaxf(am, EPSF);
    float scale = 127.0f / amax;
    char4 o4;
    o4.x = (char)fminf(fmaxf(rintf(v.x * scale), -128.f), 127.f);
    o4.y = (char)fminf(fmaxf(rintf(v.y * scale), -128.f), 127.f);
    o4.z = (char)fminf(fmaxf(rintf(v.z * scale), -128.f), 127.f);
    o4.w = (char)fminf(fmaxf(rintf(v.w * scale), -128.f), 127.f);
    *(char4*)(out + (size_t)row * 1024 + t * 4) = o4;
    if (t == 0) rowscale[row] = amax * (1.0f / 127.0f);
}

// ---------------- int8 tensor-core GEMM (128x128, 4-stage, ldmatrix frags) ----------------
__device__ __forceinline__ void mma_s8(int* c, const uint32_t* a, const uint32_t* b)
{
    asm volatile(
        "mma.sync.aligned.m16n8k32.row.col.s32.s8.s8.s32 "
        "{%0,%1,%2,%3}, {%4,%5,%6,%7}, {%8,%9}, {%0,%1,%2,%3};"
        : "+r"(c[0]), "+r"(c[1]), "+r"(c[2]), "+r"(c[3])
        : "r"(a[0]), "r"(a[1]), "r"(a[2]), "r"(a[3]), "r"(b[0]), "r"(b[1]));
}

// OUT_MODE: 0 = float, 2 = half hi/lo split.  smem: 4 stages x 20480 B = 81920 B.
template <int OUT_MODE>
__device__ __forceinline__ void gemm_body(int8_t* gsm,
                                          const int8_t* __restrict__ A,
                                          const int8_t* __restrict__ Bm,
                                          const float* __restrict__ ascale,
                                          float cmm,
                                          void* __restrict__ Cout,
                                          void* __restrict__ Cout2)
{
    int tid = threadIdx.x;
    int w = tid >> 5, lane = tid & 31;
    int grp = lane >> 2, q = lane & 3;
    int warpM = w >> 1, warpN = w & 1;
    int mBase = blockIdx.y * 128, nBase = blockIdx.x * 128;
    int lrow = lane & 15;
    int lcol = (lane >> 4) << 4;

    const int8_t* Ag = A + (size_t)mBase * 1024;
    const int8_t* Bg = Bm + (size_t)nBase * 1024;

    int acc[2][8][4];
    #pragma unroll
    for (int mf = 0; mf < 2; mf++)
        #pragma unroll
        for (int nf = 0; nf < 8; nf++)
            #pragma unroll
            for (int i = 0; i < 4; i++) acc[mf][nf][i] = 0;

    auto issue_stage = [&](int s) {
        if (s < 16) {
            int k0 = s * 64;
            int8_t* dst = gsm + (s & 3) * 20480;
            #pragma unroll
            for (int j = 0; j < 2; j++) {
                int idx = tid + j * 256;
                int row = idx >> 2, seg = idx & 3;
                uint32_t sa = (uint32_t)__cvta_generic_to_shared(dst + row * 80 + seg * 16);
                const int8_t* ga = Ag + (size_t)row * 1024 + k0 + seg * 16;
                asm volatile("cp.async.cg.shared.global [%0], [%1], 16;" :: "r"(sa), "l"(ga));
                uint32_t sb = (uint32_t)__cvta_generic_to_shared(dst + 10240 + row * 80 + seg * 16);
                const int8_t* gb = Bg + (size_t)row * 1024 + k0 + seg * 16;
                asm volatile("cp.async.cg.shared.global [%0], [%1], 16;" :: "r"(sb), "l"(gb));
            }
        }
        asm volatile("cp.async.commit_group;");
    };

    issue_stage(0);
    issue_stage(1);
    issue_stage(2);

    for (int s = 0; s < 16; s++) {
        issue_stage(s + 3);
        asm volatile("cp.async.wait_group 3;");
        __syncthreads();

        const int8_t* As = gsm + (s & 3) * 20480;
        const int8_t* Bs = As + 10240;
        #pragma unroll
        for (int ks = 0; ks < 2; ks++) {
            int koff = ks * 32;
            uint32_t afr[2][4];
            #pragma unroll
            for (int mf = 0; mf < 2; mf++) {
                const int8_t* p = As + (warpM * 32 + mf * 16 + lrow) * 80 + koff + lcol;
                ldsm4(afr[mf], p);
            }
            #pragma unroll
            for (int np = 0; np < 4; np++) {
                uint32_t bfr[4];
                const int8_t* p = Bs + (warpN * 64 + np * 16 + lrow) * 80 + koff + lcol;
                ldsm4(bfr, p);
                uint32_t be[2] = { bfr[0], bfr[2] };
                uint32_t bo[2] = { bfr[1], bfr[3] };
                mma_s8(acc[0][np * 2],     afr[0], be);
                mma_s8(acc[1][np * 2],     afr[1], be);
                mma_s8(acc[0][np * 2 + 1], afr[0], bo);
                mma_s8(acc[1][np * 2 + 1], afr[1], bo);
            }
        }
        __syncthreads();
    }

    // dequant epilogue
    #pragma unroll
    for (int mf = 0; mf < 2; mf++) {
        int row = mBase + warpM * 32 + mf * 16 + grp;
        float f0 = cmm * ascale[row];
        float f1 = cmm * ascale[row + 8];
        #pragma unroll
        for (int nf = 0; nf < 8; nf++) {
            int col = nBase + warpN * 64 + nf * 8 + 2 * q;
            float v00 = (float)acc[mf][nf][0] * f0, v01 = (float)acc[mf][nf][1] * f0;
            float v10 = (float)acc[mf][nf][2] * f1, v11 = (float)acc[mf][nf][3] * f1;
            if (OUT_MODE == 0) {
                float* O = (float*)Cout;
                *(float2*)(O + (size_t)row * 1024 + col) = make_float2(v00, v01);
                *(float2*)(O + (size_t)(row + 8) * 1024 + col) = make_float2(v10, v11);
            } else {
                __half* Oh = (__half*)Cout;
                __half* Ol = (__half*)Cout2;
                __half h00 = __float2half_rn(v00), h01 = __float2half_rn(v01);
                __half h10 = __float2half_rn(v10), h11 = __float2half_rn(v11);
                *(half2*)(Oh + (size_t)row * 1024 + col) = __halves2half2(h00, h01);
                *(half2*)(Oh + (size_t)(row + 8) * 1024 + col) = __halves2half2(h10, h11);
                __half l00 = __float2half_rn(v00 - __half2float(h00));
                __half l01 = __float2half_rn(v01 - __half2float(h01));
                __half l10 = __float2half_rn(v10 - __half2float(h10));
                __half l11 = __float2half_rn(v11 - __half2float(h11));
                *(half2*)(Ol + (size_t)row * 1024 + col) = __halves2half2(l00, l01);
                *(half2*)(Ol + (size_t)(row + 8) * 1024 + col) = __halves2half2(l10, l11);
            }
        }
    }
}

// fused Q/K/V projection: grid (8, 32, 3); all outputs hi/lo split
__global__ __launch_bounds__(256) void gemm_proj(const int8_t* __restrict__ xq,
                                                 const int8_t* __restrict__ cq,
                                                 const float* __restrict__ xs,
                                                 const float* __restrict__ cs,
                                                 const int8_t* __restrict__ wt,
                                                 __half* qh, __half* ql,
                                                 __half* kh, __half* kl,
                                                 __half* vh, __half* vl)
{
    extern __shared__ int8_t gsm[];
    int z = blockIdx.z;
    const int8_t* A = (z == 0) ? xq : cq;
    const float* as_ = (z == 0) ? xs : cs;
    const int8_t* B = wt + (size_t)z * 1048576;
    void* o1 = (z == 0) ? (void*)qh : (z == 1) ? (void*)kh : (void*)vh;
    void* o2 = (z == 0) ? (void*)ql : (z == 1) ? (void*)kl : (void*)vl;
    float cmm = g_wcm[z] * ((z == 0) ? 0.125f : 1.0f);
    gemm_body<2>(gsm, A, B, as_, cmm, o1, o2);
}

// output projection: grid (8, 32)
__global__ __launch_bounds__(256) void gemm_out(const int8_t* __restrict__ aq,
                                                const float* __restrict__ as_,
                                                const int8_t* __restrict__ wt,
                                                float* __restrict__ out)
{
    extern __shared__ int8_t gsm[];
    gemm_body<0>(gsm, aq, wt + 3145728, as_, g_wcm[3], out, nullptr);
}

// ---------------- flash attention, split hi/lo, 8 warps: q-group x kv-half ----------------
__device__ __forceinline__ void mma_f16(float* c, const uint32_t* a, const uint32_t* b)
{
    asm volatile(
        "mma.sync.aligned.m16n8k16.row.col.f32.f16.f16.f32 "
        "{%0,%1,%2,%3}, {%4,%5,%6,%7}, {%8,%9}, {%0,%1,%2,%3};"
        : "+f"(c[0]), "+f"(c[1]), "+f"(c[2]), "+f"(c[3])
        : "r"(a[0]), "r"(a[1]), "r"(a[2]), "r"(a[3]), "r"(b[0]), "r"(b[1]));
}

// grid (32 qblocks, 16 heads, 2 batch), 256 threads (8 warps), q tile 64, key chunk 64.
// Warp (g = w&3, half = w>>2): q-rows [g*16, g*16+16), keys [half*32, half*32+32) of each chunk.
// Two partial (m,l,O) per q-row merged at the end (split-KV merge through smem).
// dynamic smem: 2 stages x 4 buffers x 64x72 halfs = 73728 B; 2 blocks/SM.
__global__ __launch_bounds__(256, 2) void attn_kernel(const __half* __restrict__ Qh,
                                                      const __half* __restrict__ Ql,
                                                      const __half* __restrict__ Kh,
                                                      const __half* __restrict__ Kl,
                                                      const __half* __restrict__ Vh,
                                                      const __half* __restrict__ Vl,
                                                      float* __restrict__ Oout)
{
    const int STR = 72;
    const int BUF = 64 * STR;            // 4608 halfs = 9216 bytes
    extern __shared__ __half smema[];    // [2][4][BUF]

    int b = blockIdx.z, h = blockIdx.y, qb = blockIdx.x;
    int tid = threadIdx.x;
    int w = tid >> 5, lane = tid & 31;
    int grp = lane >> 2, q = lane & 3;
    int g = w & 3, half = w >> 2;

    size_t qoff = (size_t)(b * 2048 + qb * 64) * 1024 + h * 64;
    size_t koff = (size_t)b * 2048 * 1024 + h * 64;

    // ---- stage Q hi AND lo through smem concurrently ----
    uint32_t aQh[4][4], aQl[4][4];
    {
        __half* Qsh = smema;
        __half* Qsl = smema + BUF;
        #pragma unroll
        for (int j = 0; j < 2; j++) {
            int idx = tid + j * 256;
            int row = idx >> 3, seg = idx & 7;
            *(int4*)&Qsh[row * STR + seg * 8] = *(const int4*)(Qh + qoff + (size_t)row * 1024 + seg * 8);
            *(int4*)&Qsl[row * STR + seg * 8] = *(const int4*)(Ql + qoff + (size_t)row * 1024 + seg * 8);
        }
        __syncthreads();
        #pragma unroll
        for (int kf = 0; kf < 4; kf++) {
            int r = g * 16 + (lane & 15);
            int c = kf * 16 + ((lane >> 4) << 3);
            ldsm4(aQh[kf], &Qsh[r * STR + c]);
            ldsm4(aQl[kf], &Qsl[r * STR + c]);
        }
        __syncthreads();   // Q frags in regs; smem free for the pipeline
    }

    // K/V prefetch: stage st holds Ksh|Ksl|Vsh|Vsl each BUF halfs
    auto issue_kv = [&](int s, int st) {
        int j0 = s * 64;
        __half* base = smema + st * 4 * BUF;
        #pragma unroll
        for (int j = 0; j < 2; j++) {
            int idx = tid + j * 256;
            int row = idx >> 3, seg = idx & 7;
            size_t gaddr = koff + (size_t)(j0 + row) * 1024 + seg * 8;
            uint32_t d = (uint32_t)__cvta_generic_to_shared(base + row * STR + seg * 8);
            asm volatile("cp.async.cg.shared.global [%0], [%1], 16;" :: "r"(d), "l"(Kh + gaddr));
            asm volatile("cp.async.cg.shared.global [%0], [%1], 16;" :: "r"(d + 9216u), "l"(Kl + gaddr));
            asm volatile("cp.async.cg.shared.global [%0], [%1], 16;" :: "r"(d + 18432u), "l"(Vh + gaddr));
            asm volatile("cp.async.cg.shared.global [%0], [%1], 16;" :: "r"(d + 27648u), "l"(Vl + gaddr));
        }
        asm volatile("cp.async.commit_group;");
    };

    issue_kv(0, 0);

    float m0 = -1e30f, m1 = -1e30f, l0 = 0.f, l1 = 0.f;
    float o[8][4];
    #pragma unroll
    for (int nf = 0; nf < 8; nf++)
        #pragma unroll
        for (int i = 0; i < 4; i++) o[nf][i] = 0.f;

    for (int t = 0; t < 32; t++) {
        int buf = t & 1;
        if (t < 31) {
            issue_kv(t + 1, buf ^ 1);
            asm volatile("cp.async.wait_group 1;");
        } else {
            asm volatile("cp.async.wait_group 0;");
        }
        __syncthreads();

        const __half* Ksh = smema + buf * 4 * BUF;
        const __half* Ksl = Ksh + BUF;
        const __half* Vsh = Ksh + 2 * BUF;
        const __half* Vsl = Ksh + 3 * BUF;

        // S = Q K^T split precision (16 rows x THIS WARP'S 32 keys)
        float s[4][4];
        #pragma unroll
        for (int nf = 0; nf < 4; nf++)
            #pragma unroll
            for (int i = 0; i < 4; i++) s[nf][i] = 0.f;

        #pragma unroll
        for (int kf = 0; kf < 4; kf++) {
            #pragma unroll
            for (int np = 0; np < 2; np++) {
                int n = half * 32 + np * 16 + (lane & 7) + ((lane >> 4) & 1) * 8;
                int c = kf * 16 + ((lane >> 3) & 1) * 8;
                uint32_t bKh[4], bKl[4];
                ldsm4(bKh, &Ksh[n * STR + c]);
                ldsm4(bKl, &Ksl[n * STR + c]);
                mma_f16(s[np * 2],     aQh[kf], &bKh[0]);
                mma_f16(s[np * 2 + 1], aQh[kf], &bKh[2]);
                mma_f16(s[np * 2],     aQh[kf], &bKl[0]);
                mma_f16(s[np * 2 + 1], aQh[kf], &bKl[2]);
                mma_f16(s[np * 2],     aQl[kf], &bKh[0]);
                mma_f16(s[np * 2 + 1], aQl[kf], &bKh[2]);
            }
        }

        // online softmax over this warp's 32-key subset (rows grp, grp+8)
        float mx0 = -1e30f, mx1 = -1e30f;
        #pragma unroll
        for (int nf = 0; nf < 4; nf++) {
            mx0 = fmaxf(mx0, fmaxf(s[nf][0], s[nf][1]));
            mx1 = fmaxf(mx1, fmaxf(s[nf][2], s[nf][3]));
        }
        mx0 = fmaxf(mx0, __shfl_xor_sync(0xffffffffu, mx0, 1));
        mx0 = fmaxf(mx0, __shfl_xor_sync(0xffffffffu, mx0, 2));
        mx1 = fmaxf(mx1, __shfl_xor_sync(0xffffffffu, mx1, 1));
        mx1 = fmaxf(mx1, __shfl_xor_sync(0xffffffffu, mx1, 2));
        float mn0 = fmaxf(m0, mx0), mn1 = fmaxf(m1, mx1);
        float corr0 = __expf(m0 - mn0), corr1 = __expf(m1 - mn1);
        m0 = mn0; m1 = mn1;

        float ps0 = 0.f, ps1 = 0.f;
        uint32_t aPh[2][4], aPl[2][4];
        #pragma unroll
        for (int nf = 0; nf < 4; nf++) {
            float p0 = __expf(s[nf][0] - mn0);
            float p1 = __expf(s[nf][1] - mn0);
            float p2 = __expf(s[nf][2] - mn1);
            float p3 = __expf(s[nf][3] - mn1);
            ps0 += p0 + p1; ps1 += p2 + p3;
            __half h0 = __float2half_rn(p0), h1 = __float2half_rn(p1);
            __half h2 = __float2half_rn(p2), h3 = __float2half_rn(p3);
            __half e0 = __float2half_rn(p0 - __half2float(h0));
            __half e1 = __float2half_rn(p1 - __half2float(h1));
            __half e2 = __float2half_rn(p2 - __half2float(h2));
            __half e3 = __float2half_rn(p3 - __half2float(h3));
            int kf = nf >> 1, hi = nf & 1;
            half2 hh01 = __halves2half2(h0, h1), hh23 = __halves2half2(h2, h3);
            half2 ll01 = __halves2half2(e0, e1), ll23 = __halves2half2(e2, e3);
            aPh[kf][hi * 2]     = *(uint32_t*)&hh01;
            aPh[kf][hi * 2 + 1] = *(uint32_t*)&hh23;
            aPl[kf][hi * 2]     = *(uint32_t*)&ll01;
            aPl[kf][hi * 2 + 1] = *(uint32_t*)&ll23;
        }
        ps0 += __shfl_xor_sync(0xffffffffu, ps0, 1);
        ps0 += __shfl_xor_sync(0xffffffffu, ps0, 2);
        ps1 += __shfl_xor_sync(0xffffffffu, ps1, 1);
        ps1 += __shfl_xor_sync(0xffffffffu, ps1, 2);
        l0 = l0 * corr0 + ps0;
        l1 = l1 * corr1 + ps1;
        #pragma unroll
        for (int nf = 0; nf < 8; nf++) {
            o[nf][0] *= corr0; o[nf][1] *= corr0;
            o[nf][2] *= corr1; o[nf][3] *= corr1;
        }

        // O += P V split precision over this warp's 32 keys (2 k-frags)
        #pragma unroll
        for (int kf = 0; kf < 2; kf++) {
            #pragma unroll
            for (int np = 0; np < 4; np++) {
                int kr = half * 32 + kf * 16 + (lane & 7) + ((lane >> 3) & 1) * 8;
                int c = np * 16 + ((lane >> 4) & 1) * 8;
                uint32_t bVh[4], bVl[4];
                ldsm4t(bVh, &Vsh[kr * STR + c]);
                ldsm4t(bVl, &Vsl[kr * STR + c]);
                mma_f16(o[np * 2],     aPh[kf], &bVh[0]);
                mma_f16(o[np * 2 + 1], aPh[kf], &bVh[2]);
                mma_f16(o[np * 2],     aPh[kf], &bVl[0]);
                mma_f16(o[np * 2 + 1], aPh[kf], &bVl[2]);
                mma_f16(o[np * 2],     aPl[kf], &bVh[0]);
                mma_f16(o[np * 2 + 1], aPl[kf], &bVh[2]);
            }
        }
        __syncthreads();
    }

    // ---- merge the two kv-halves per q-row (split-KV combine through smem) ----
    float* Os = (float*)smema;                 // [64][68] fp32 partial O (half=1 warps)
    float* Ml = (float*)smema + 64 * 68;       // [64][2] m,l (half=1 warps)
    int r0 = g * 16 + grp, r1 = r0 + 8;

    if (half == 1) {
        #pragma unroll
        for (int nf = 0; nf < 8; nf++) {
            int c = nf * 8 + 2 * q;
            *(float2*)&Os[r0 * 68 + c] = make_float2(o[nf][0], o[nf][1]);
            *(float2*)&Os[r1 * 68 + c] = make_float2(o[nf][2], o[nf][3]);
        }
        if (q == 0) {
            Ml[r0 * 2] = m0; Ml[r0 * 2 + 1] = l0;
            Ml[r1 * 2] = m1; Ml[r1 * 2 + 1] = l1;
        }
    }
    __syncthreads();

    if (half == 0) {
        float pm0 = Ml[r0 * 2], pl0 = Ml[r0 * 2 + 1];
        float pm1 = Ml[r1 * 2], pl1 = Ml[r1 * 2 + 1];
        float M0 = fmaxf(m0, pm0), M1 = fmaxf(m1, pm1);
        float ca0 = __expf(m0 - M0), cb0 = __expf(pm0 - M0);
        float ca1 = __expf(m1 - M1), cb1 = __expf(pm1 - M1);
        float L0 = l0 * ca0 + pl0 * cb0;
        float L1 = l1 * ca1 + pl1 * cb1;
        float i0 = 1.0f / L0, i1 = 1.0f / L1;
        int row0 = b * 2048 + qb * 64 + r0;
        #pragma unroll
        for (int nf = 0; nf < 8; nf++) {
            int c = nf * 8 + 2 * q;
            float2 b0 = *(float2*)&Os[r0 * 68 + c];
            float2 b1 = *(float2*)&Os[r1 * 68 + c];
            int col = h * 64 + c;
            *(float2*)(Oout + (size_t)row0 * 1024 + col) =
                make_float2((o[nf][0] * ca0 + b0.x * cb0) * i0, (o[nf][1] * ca0 + b0.y * cb0) * i0);
            *(float2*)(Oout + (size_t)(row0 + 8) * 1024 + col) =
                make_float2((o[nf][2] * ca1 + b1.x * cb1) * i1, (o[nf][3] * ca1 + b1.y * cb1) * i1);
        }
    }
}

// ---------------- single-input act quant (attention output) ----------------
__global__ __launch_bounds__(256) void act_quant_i8(const float* __restrict__ in,
                                                    int8_t* __restrict__ out,
                                                    float* __restrict__ rowscale)
{
    int row = blockIdx.x;
    int t = threadIdx.x;
    const float4* ri = (const float4*)(in + (size_t)row * 1024);
    float4 v = ri[t];
    float am = fmaxf(fmaxf(fabsf(v.x), fabsf(v.y)), fmaxf(fabsf(v.z), fabsf(v.w)));
    #pragma unroll
    for (int o = 16; o > 0; o >>= 1) am = fmaxf(am, __shfl_xor_sync(0xffffffffu, am, o));
    __shared__ float wm[8];
    if ((t & 31) == 0) wm[t >> 5] = am;
    __syncthreads();
    am = wm[0];
    #pragma unroll
    for (int i = 1; i < 8; i++) am = fmaxf(am, wm[i]);
    float amax = fmaxf(am, EPSF);
    float scale = 127.0f / amax;
    char4 o4;
    o4.x = (char)fminf(fmaxf(rintf(v.x * scale), -128.f), 127.f);
    o4.y = (char)fminf(fmaxf(rintf(v.y * scale), -128.f), 127.f);
    o4.z = (char)fminf(fmaxf(rintf(v.z * scale), -128.f), 127.f);
    o4.w = (char)fminf(fmaxf(rintf(v.w * scale), -128.f), 127.f);
    *(char4*)(out + (size_t)row * 1024 + t * 4) = o4;
    if (t == 0) rowscale[row] = amax * (1.0f / 127.0f);
}

// ---------------- launch ----------------
extern "C" void kernel_launch(void* const* d_in, const int* in_sizes, int n_in,
                              void* d_out, int out_size)
{
    (void)in_sizes; (void)n_in; (void)out_size;
    const float* x   = (const float*)d_in[0];
    const float* ctx = (const float*)d_in[1];
    const float* wq  = (const float*)d_in[2];
    const float* wk  = (const float*)d_in[3];
    const float* wv  = (const float*)d_in[4];
    const float* wo  = (const float*)d_in[5];
    float* out = (float*)d_out;

    int8_t *xq, *cq, *aq, *wt;
    float *xs, *cs, *as, *attn;
    __half *qh, *ql, *kh, *kl, *vh, *vl;
    cudaGetSymbolAddress((void**)&xq, g_xq);
    cudaGetSymbolAddress((void**)&cq, g_cq);
    cudaGetSymbolAddress((void**)&aq, g_aq);
    cudaGetSymbolAddress((void**)&wt, g_wt);
    cudaGetSymbolAddress((void**)&xs, g_xscale);
    cudaGetSymbolAddress((void**)&cs, g_cscale);
    cudaGetSymbolAddress((void**)&as, g_ascale);
    cudaGetSymbolAddress((void**)&qh, g_qh);
    cudaGetSymbolAddress((void**)&ql, g_ql);
    cudaGetSymbolAddress((void**)&kh, g_kh);
    cudaGetSymbolAddress((void**)&kl, g_kl);
    cudaGetSymbolAddress((void**)&vh, g_vh);
    cudaGetSymbolAddress((void**)&vl, g_vl);
    cudaGetSymbolAddress((void**)&attn, g_attn);

    // opt-in dynamic smem (host-side attribute set; idempotent, capture-safe)
    cudaFuncSetAttribute(gemm_proj, cudaFuncAttributeMaxDynamicSharedMemorySize, 81920);
    cudaFuncSetAttribute(gemm_out,  cudaFuncAttributeMaxDynamicSharedMemorySize, 81920);
    cudaFuncSetAttribute(attn_kernel, cudaFuncAttributeMaxDynamicSharedMemorySize, 73728);

    // weight quantization (ternary int8); scale computation fused into wquant
    wsum_kernel<<<dim3(64, 4), 256>>>(wq, wk, wv, wo);
    wquant_kernel<<<dim3(1024, 4), 256>>>(wq, wk, wv, wo);

    // activation quantization (x and ctx fused)
    act_quant2_i8<<<dim3(4096, 2), 256>>>(x, ctx, xq, cq, xs, cs);

    // fused Q/K/V projections (int8 IMMA, 128x128 tiles, ldmatrix frags); Q pre-scaled 0.125
    gemm_proj<<<dim3(8, 32, 3), 256, 81920>>>(xq, cq, xs, cs, wt, qh, ql, kh, kl, vh, vl);

    // attention (HMMA flash, split QK^T and P.V, 8 warps: 4 q-groups x 2 kv-halves)
    attn_kernel<<<dim3(32, 16, 2), 256, 73728>>>(qh, ql, kh, kl, vh, vl, attn);

    // output projection
    act_quant_i8<<<4096, 256>>>(attn, aq, as);
    gemm_out<<<dim3(8, 32), 256, 81920>>>(aq, as, wt, out);
}

// round 14
// speedup vs baseline: 1.0787x; 1.0787x over previous
#include <cuda_runtime.h>
#include <cuda_fp16.h>
#include <math.h>
#include <stdint.h>

#define EPSF 1e-5f

// ---------------- scratch ----------------
__device__ int8_t g_xq[4194304];     // quantized x int8 [4096,1024]
__device__ int8_t g_cq[4194304];     // quantized context int8
__device__ int8_t g_aq[4194304];     // quantized attn-out int8
__device__ int8_t g_wt[4][1048576];  // ternary weights int8 (q,k,v,o)
__device__ float  g_xscale[4096];
__device__ float  g_cscale[4096];
__device__ float  g_ascale[4096];
__device__ __half g_qh[4194304];     // Q hi fp16 (pre-scaled by 0.125)
__device__ __half g_ql[4194304];     // Q lo fp16 (residual)
__device__ __half g_kh[4194304];     // K hi
__device__ __half g_kl[4194304];     // K lo
__device__ __half g_vh[4194304];     // V hi
__device__ __half g_vl[4194304];     // V lo
__device__ float  g_attn[4194304];   // attention output fp32
__device__ double g_wpart[256];
__device__ float  g_wcm[4];
__device__ float  g_wscale[4];

// ---------------- weight |w| sum (double accumulation, deterministic) ----------------
__global__ __launch_bounds__(256) void wsum_kernel(const float* __restrict__ w0,
                                                   const float* __restrict__ w1,
                                                   const float* __restrict__ w2,
                                                   const float* __restrict__ w3)
{
    const float* w = (blockIdx.y == 0) ? w0 : (blockIdx.y == 1) ? w1 : (blockIdx.y == 2) ? w2 : w3;
    int base = blockIdx.x * 16384;
    int t = threadIdx.x;
    double s = 0.0;
    #pragma unroll
    for (int i = 0; i < 16; i++) {
        float4 v = *(const float4*)(w + base + i * 1024 + t * 4);
        s += (double)fabsf(v.x) + (double)fabsf(v.y) + (double)fabsf(v.z) + (double)fabsf(v.w);
    }
    #pragma unroll
    for (int o = 16; o > 0; o >>= 1) s += __shfl_down_sync(0xffffffffu, s, o);
    __shared__ double ws[8];
    if ((t & 31) == 0) ws[t >> 5] = s;
    __syncthreads();
    if (t == 0) {
        double tot = 0.0;
        #pragma unroll
        for (int i = 0; i < 8; i++) tot += ws[i];
        g_wpart[blockIdx.y * 64 + blockIdx.x] = tot;
    }
}

// wquant with fused scale computation (each block recomputes the deterministic mean)
__global__ __launch_bounds__(256) void wquant_kernel(const float* __restrict__ w0,
                                                     const float* __restrict__ w1,
                                                     const float* __restrict__ w2,
                                                     const float* __restrict__ w3)
{
    int m = blockIdx.y;
    const float* w = (m == 0) ? w0 : (m == 1) ? w1 : (m == 2) ? w2 : w3;
    __shared__ float sh_s;
    if (threadIdx.x == 0) {
        double tot = 0.0;
        #pragma unroll 8
        for (int i = 0; i < 64; i++) tot += g_wpart[m * 64 + i];
        float mean = (float)(tot / 1048576.0);
        float cm = fmaxf(mean, EPSF);
        sh_s = 1.0f / cm;
        if (blockIdx.x == 0) {          // publish for GEMM epilogues (deterministic value)
            g_wcm[m] = cm;
            g_wscale[m] = 1.0f / cm;
        }
    }
    __syncthreads();
    float s = sh_s;
    int idx = (blockIdx.x * 256 + threadIdx.x) * 4;
    float4 v = *(const float4*)(w + idx);
    char4 o;
    o.x = (char)fminf(fmaxf(rintf(v.x * s), -1.f), 1.f);
    o.y = (char)fminf(fmaxf(rintf(v.y * s), -1.f), 1.f);
    o.z = (char)fminf(fmaxf(rintf(v.z * s), -1.f), 1.f);
    o.w = (char)fminf(fmaxf(rintf(v.w * s), -1.f), 1.f);
    *(char4*)(g_wt[m] + idx) = o;
}

// ---------------- per-token int8 absmax quant (fused x+ctx via grid.y) ----------------
__global__ __launch_bounds__(256) void act_quant2_i8(const float* __restrict__ in0,
                                                     const float* __restrict__ in1,
                                                     int8_t* __restrict__ out0,
                                                     int8_t* __restrict__ out1,
                                                     float* __restrict__ rs0,
                                                     float* __restrict__ rs1)
{
    const float* in = blockIdx.y ? in1 : in0;
    int8_t* out = blockIdx.y ? out1 : out0;
    float* rowscale = blockIdx.y ? rs1 : rs0;
    int row = blockIdx.x;
    int t = threadIdx.x;
    const float4* ri = (const float4*)(in + (size_t)row * 1024);
    float4 v = ri[t];
    float am = fmaxf(fmaxf(fabsf(v.x), fabsf(v.y)), fmaxf(fabsf(v.z), fabsf(v.w)));
    #pragma unroll
    for (int o = 16; o > 0; o >>= 1) am = fmaxf(am, __shfl_xor_sync(0xffffffffu, am, o));
    __shared__ float wm[8];
    if ((t & 31) == 0) wm[t >> 5] = am;
    __syncthreads();
    am = wm[0];
    #pragma unroll
    for (int i = 1; i < 8; i++) am = fmaxf(am, wm[i]);
    float amax = fmaxf(am, EPSF);
    float scale = 127.0f / amax;
    char4 o4;
    o4.x = (char)fminf(fmaxf(rintf(v.x * scale), -128.f), 127.f);
    o4.y = (char)fminf(fmaxf(rintf(v.y * scale), -128.f), 127.f);
    o4.z = (char)fminf(fmaxf(rintf(v.z * scale), -128.f), 127.f);
    o4.w = (char)fminf(fmaxf(rintf(v.w * scale), -128.f), 127.f);
    *(char4*)(out + (size_t)row * 1024 + t * 4) = o4;
    if (t == 0) rowscale[row] = amax * (1.0f / 127.0f);
}

// ---------------- int8 tensor-core GEMM core (4-stage cp.async pipeline) ----------------
__device__ __forceinline__ void mma_s8(int* c, const uint32_t* a, const uint32_t* b)
{
    asm volatile(
        "mma.sync.aligned.m16n8k32.row.col.s32.s8.s8.s32 "
        "{%0,%1,%2,%3}, {%4,%5,%6,%7}, {%8,%9}, {%0,%1,%2,%3};"
        : "+r"(c[0]), "+r"(c[1]), "+r"(c[2]), "+r"(c[3])
        : "r"(a[0]), "r"(a[1]), "r"(a[2]), "r"(a[3]), "r"(b[0]), "r"(b[1]));
}

// OUT_MODE: 0 = float, 2 = half hi/lo split.  smem: 4 stages x 20480 B.
template <int OUT_MODE>
__device__ __forceinline__ void gemm_body(int8_t* gsm,
                                          const int8_t* __restrict__ A,
                                          const int8_t* __restrict__ Bm,
                                          const float* __restrict__ ascale,
                                          float cmm,
                                          void* __restrict__ Cout,
                                          void* __restrict__ Cout2)
{
    int tid = threadIdx.x;
    int w = tid >> 5, lane = tid & 31;
    int grp = lane >> 2, q = lane & 3;
    int warpM = w >> 1, warpN = w & 1;
    int mBase = blockIdx.y * 128, nBase = blockIdx.x * 128;

    const int8_t* Ag = A + (size_t)mBase * 1024;
    const int8_t* Bg = Bm + (size_t)nBase * 1024;

    int acc[2][8][4];
    #pragma unroll
    for (int mf = 0; mf < 2; mf++)
        #pragma unroll
        for (int nf = 0; nf < 8; nf++)
            #pragma unroll
            for (int i = 0; i < 4; i++) acc[mf][nf][i] = 0;

    auto issue_stage = [&](int s) {
        if (s < 16) {
            int k0 = s * 64;
            int8_t* dst = gsm + (s & 3) * 20480;
            #pragma unroll
            for (int j = 0; j < 2; j++) {
                int idx = tid + j * 256;
                int row = idx >> 2, seg = idx & 3;
                uint32_t sa = (uint32_t)__cvta_generic_to_shared(dst + row * 80 + seg * 16);
                const int8_t* ga = Ag + (size_t)row * 1024 + k0 + seg * 16;
                asm volatile("cp.async.cg.shared.global [%0], [%1], 16;" :: "r"(sa), "l"(ga));
                uint32_t sb = (uint32_t)__cvta_generic_to_shared(dst + 10240 + row * 80 + seg * 16);
                const int8_t* gb = Bg + (size_t)row * 1024 + k0 + seg * 16;
                asm volatile("cp.async.cg.shared.global [%0], [%1], 16;" :: "r"(sb), "l"(gb));
            }
        }
        asm volatile("cp.async.commit_group;");   // always commit (possibly empty)
    };

    issue_stage(0);
    issue_stage(1);
    issue_stage(2);

    for (int s = 0; s < 16; s++) {
        issue_stage(s + 3);
        asm volatile("cp.async.wait_group 3;");
        __syncthreads();

        const int8_t* As = gsm + (s & 3) * 20480;
        const int8_t* Bs = As + 10240;
        #pragma unroll
        for (int ks = 0; ks < 2; ks++) {
            int koff = ks * 32;
            uint32_t afr[2][4];
            #pragma unroll
            for (int mf = 0; mf < 2; mf++) {
                int rowb = warpM * 32 + mf * 16 + grp;
                const int8_t* p = As + rowb * 80 + koff + 4 * q;
                afr[mf][0] = *(const uint32_t*)p;
                afr[mf][1] = *(const uint32_t*)(p + 8 * 80);
                afr[mf][2] = *(const uint32_t*)(p + 16);
                afr[mf][3] = *(const uint32_t*)(p + 8 * 80 + 16);
            }
            #pragma unroll
            for (int nf = 0; nf < 8; nf++) {
                int nb = warpN * 64 + nf * 8 + grp;
                const int8_t* p = Bs + nb * 80 + koff + 4 * q;
                uint32_t bfr[2];
                bfr[0] = *(const uint32_t*)p;
                bfr[1] = *(const uint32_t*)(p + 16);
                mma_s8(acc[0][nf], afr[0], bfr);
                mma_s8(acc[1][nf], afr[1], bfr);
            }
        }
        __syncthreads();
    }

    // dequant epilogue: val = s32 * cm * (amax_row/127) * mult (exact in fp32)
    #pragma unroll
    for (int mf = 0; mf < 2; mf++) {
        int row = mBase + warpM * 32 + mf * 16 + grp;
        float f0 = cmm * ascale[row];
        float f1 = cmm * ascale[row + 8];
        #pragma unroll
        for (int nf = 0; nf < 8; nf++) {
            int col = nBase + warpN * 64 + nf * 8 + 2 * q;
            float v00 = (float)acc[mf][nf][0] * f0, v01 = (float)acc[mf][nf][1] * f0;
            float v10 = (float)acc[mf][nf][2] * f1, v11 = (float)acc[mf][nf][3] * f1;
            if (OUT_MODE == 0) {
                float* O = (float*)Cout;
                *(float2*)(O + (size_t)row * 1024 + col) = make_float2(v00, v01);
                *(float2*)(O + (size_t)(row + 8) * 1024 + col) = make_float2(v10, v11);
            } else {
                __half* Oh = (__half*)Cout;
                __half* Ol = (__half*)Cout2;
                __half h00 = __float2half_rn(v00), h01 = __float2half_rn(v01);
                __half h10 = __float2half_rn(v10), h11 = __float2half_rn(v11);
                *(half2*)(Oh + (size_t)row * 1024 + col) = __halves2half2(h00, h01);
                *(half2*)(Oh + (size_t)(row + 8) * 1024 + col) = __halves2half2(h10, h11);
                __half l00 = __float2half_rn(v00 - __half2float(h00));
                __half l01 = __float2half_rn(v01 - __half2float(h01));
                __half l10 = __float2half_rn(v10 - __half2float(h10));
                __half l11 = __float2half_rn(v11 - __half2float(h11));
                *(half2*)(Ol + (size_t)row * 1024 + col) = __halves2half2(l00, l01);
                *(half2*)(Ol + (size_t)(row + 8) * 1024 + col) = __halves2half2(l10, l11);
            }
        }
    }
}

// fused Q/K/V projection: grid (8, 32, 3)
__global__ __launch_bounds__(256) void gemm_proj(const int8_t* __restrict__ xq,
                                                 const int8_t* __restrict__ cq,
                                                 const float* __restrict__ xs,
                                                 const float* __restrict__ cs,
                                                 const int8_t* __restrict__ wt,
                                                 __half* qh, __half* ql,
                                                 __half* kh, __half* kl,
                                                 __half* vh, __half* vl)
{
    extern __shared__ int8_t gsm[];
    int z = blockIdx.z;
    const int8_t* A = (z == 0) ? xq : cq;
    const float* as_ = (z == 0) ? xs : cs;
    const int8_t* B = wt + (size_t)z * 1048576;
    void* o1 = (z == 0) ? (void*)qh : (z == 1) ? (void*)kh : (void*)vh;
    void* o2 = (z == 0) ? (void*)ql : (z == 1) ? (void*)kl : (void*)vl;
    float cmm = g_wcm[z] * ((z == 0) ? 0.125f : 1.0f);
    gemm_body<2>(gsm, A, B, as_, cmm, o1, o2);
}

// output projection: grid (8, 32)
__global__ __launch_bounds__(256) void gemm_out(const int8_t* __restrict__ aq,
                                                const float* __restrict__ as_,
                                                const int8_t* __restrict__ wt,
                                                float* __restrict__ out)
{
    extern __shared__ int8_t gsm[];
    gemm_body<0>(gsm, aq, wt + 3145728, as_, g_wcm[3], out, nullptr);
}

// ---------------- flash attention, split-fp16 hi/lo, double-buffered K/V ----------------
__device__ __forceinline__ void mma_f16(float* c, const uint32_t* a, const uint32_t* b)
{
    asm volatile(
        "mma.sync.aligned.m16n8k16.row.col.f32.f16.f16.f32 "
        "{%0,%1,%2,%3}, {%4,%5,%6,%7}, {%8,%9}, {%0,%1,%2,%3};"
        : "+f"(c[0]), "+f"(c[1]), "+f"(c[2]), "+f"(c[3])
        : "r"(a[0]), "r"(a[1]), "r"(a[2]), "r"(a[3]), "r"(b[0]), "r"(b[1]));
}

__device__ __forceinline__ void ldsm4(uint32_t* r, const void* p)
{
    uint32_t a = (uint32_t)__cvta_generic_to_shared(p);
    asm volatile("ldmatrix.sync.aligned.m8n8.x4.shared.b16 {%0,%1,%2,%3}, [%4];"
                 : "=r"(r[0]), "=r"(r[1]), "=r"(r[2]), "=r"(r[3]) : "r"(a));
}

__device__ __forceinline__ void ldsm4t(uint32_t* r, const void* p)
{
    uint32_t a = (uint32_t)__cvta_generic_to_shared(p);
    asm volatile("ldmatrix.sync.aligned.m8n8.x4.trans.shared.b16 {%0,%1,%2,%3}, [%4];"
                 : "=r"(r[0]), "=r"(r[1]), "=r"(r[2]), "=r"(r[3]) : "r"(a));
}

// grid (32 qblocks, 16 heads, 2 batch), 128 threads (4 warps).
// dynamic smem: 2 stages x 4 buffers (Ksh,Ksl,Vsh,Vsl) x 64x72 halfs = 73728 B; 3 blocks/SM.
__global__ __launch_bounds__(128, 3) void attn_kernel(const __half* __restrict__ Qh,
                                                      const __half* __restrict__ Ql,
                                                      const __half* __restrict__ Kh,
                                                      const __half* __restrict__ Kl,
                                                      const __half* __restrict__ Vh,
                                                      const __half* __restrict__ Vl,
                                                      float* __restrict__ Oout)
{
    const int STR = 72;
    const int BUF = 64 * STR;            // 4608 halfs = 9216 bytes
    extern __shared__ __half smema[];    // [2][4][BUF]

    int b = blockIdx.z, h = blockIdx.y, qb = blockIdx.x;
    int tid = threadIdx.x;
    int w = tid >> 5, lane = tid & 31;
    int grp = lane >> 2, q = lane & 3;

    size_t qoff = (size_t)(b * 2048 + qb * 64) * 1024 + h * 64;
    size_t koff = (size_t)b * 2048 * 1024 + h * 64;

    // ---- stage Q hi/lo through smem (before cp.async pipeline touches it) ----
    uint32_t aQh[4][4], aQl[4][4];
    {
        __half* Qs = smema;
        #pragma unroll
        for (int j = 0; j < 4; j++) {
            int idx = tid + j * 128;
            int row = idx >> 3, seg = idx & 7;
            *(int4*)&Qs[row * STR + seg * 8] = *(const int4*)(Qh + qoff + (size_t)row * 1024 + seg * 8);
        }
        __syncthreads();
        #pragma unroll
        for (int kf = 0; kf < 4; kf++) {
            int r = w * 16 + (lane & 15);
            int c = kf * 16 + ((lane >> 4) << 3);
            ldsm4(aQh[kf], &Qs[r * STR + c]);
        }
        __syncthreads();
        #pragma unroll
        for (int j = 0; j < 4; j++) {
            int idx = tid + j * 128;
            int row = idx >> 3, seg = idx & 7;
            *(int4*)&Qs[row * STR + seg * 8] = *(const int4*)(Ql + qoff + (size_t)row * 1024 + seg * 8);
        }
        __syncthreads();
        #pragma unroll
        for (int kf = 0; kf < 4; kf++) {
            int r = w * 16 + (lane & 15);
            int c = kf * 16 + ((lane >> 4) << 3);
            ldsm4(aQl[kf], &Qs[r * STR + c]);
        }
        __syncthreads();   // Q frags in regs; smem free for the pipeline
    }

    // K/V prefetch: stage st holds Ksh|Ksl|Vsh|Vsl each BUF halfs
    auto issue_kv = [&](int s, int st) {
        int j0 = s * 64;
        __half* base = smema + st * 4 * BUF;
        #pragma unroll
        for (int j = 0; j < 4; j++) {
            int idx = tid + j * 128;
            int row = idx >> 3, seg = idx & 7;
            size_t g = koff + (size_t)(j0 + row) * 1024 + seg * 8;
            uint32_t d = (uint32_t)__cvta_generic_to_shared(base + row * STR + seg * 8);
            asm volatile("cp.async.cg.shared.global [%0], [%1], 16;" :: "r"(d), "l"(Kh + g));
            asm volatile("cp.async.cg.shared.global [%0], [%1], 16;" :: "r"(d + 9216u), "l"(Kl + g));
            asm volatile("cp.async.cg.shared.global [%0], [%1], 16;" :: "r"(d + 18432u), "l"(Vh + g));
            asm volatile("cp.async.cg.shared.global [%0], [%1], 16;" :: "r"(d + 27648u), "l"(Vl + g));
        }
        asm volatile("cp.async.commit_group;");
    };

    issue_kv(0, 0);

    float m0 = -1e30f, m1 = -1e30f, l0 = 0.f, l1 = 0.f;
    float o[8][4];
    #pragma unroll
    for (int nf = 0; nf < 8; nf++)
        #pragma unroll
        for (int i = 0; i < 4; i++) o[nf][i] = 0.f;

    for (int t = 0; t < 32; t++) {
        int buf = t & 1;
        if (t < 31) {
            issue_kv(t + 1, buf ^ 1);
            asm volatile("cp.async.wait_group 1;");
        } else {
            asm volatile("cp.async.wait_group 0;");
        }
        __syncthreads();

        const __half* Ksh = smema + buf * 4 * BUF;
        const __half* Ksl = Ksh + BUF;
        const __half* Vsh = Ksh + 2 * BUF;
        const __half* Vsl = Ksh + 3 * BUF;

        // S = Q K^T split precision (16 rows x 64 keys per warp)
        float s[8][4];
        #pragma unroll
        for (int nf = 0; nf < 8; nf++)
            #pragma unroll
            for (int i = 0; i < 4; i++) s[nf][i] = 0.f;

        #pragma unroll
        for (int kf = 0; kf < 4; kf++) {
            #pragma unroll
            for (int np = 0; np < 4; np++) {
                int n = np * 16 + (lane & 7) + ((lane >> 4) & 1) * 8;
                int c = kf * 16 + ((lane >> 3) & 1) * 8;
                uint32_t bKh[4], bKl[4];
                ldsm4(bKh, &Ksh[n * STR + c]);
                ldsm4(bKl, &Ksl[n * STR + c]);
                mma_f16(s[np * 2],     aQh[kf], &bKh[0]);
                mma_f16(s[np * 2 + 1], aQh[kf], &bKh[2]);
                mma_f16(s[np * 2],     aQh[kf], &bKl[0]);
                mma_f16(s[np * 2 + 1], aQh[kf], &bKl[2]);
                mma_f16(s[np * 2],     aQl[kf], &bKh[0]);
                mma_f16(s[np * 2 + 1], aQl[kf], &bKh[2]);
            }
        }

        // online softmax (rows grp, grp+8 of this warp's 16)
        float mx0 = -1e30f, mx1 = -1e30f;
        #pragma unroll
        for (int nf = 0; nf < 8; nf++) {
            mx0 = fmaxf(mx0, fmaxf(s[nf][0], s[nf][1]));
            mx1 = fmaxf(mx1, fmaxf(s[nf][2], s[nf][3]));
        }
        mx0 = fmaxf(mx0, __shfl_xor_sync(0xffffffffu, mx0, 1));
        mx0 = fmaxf(mx0, __shfl_xor_sync(0xffffffffu, mx0, 2));
        mx1 = fmaxf(mx1, __shfl_xor_sync(0xffffffffu, mx1, 1));
        mx1 = fmaxf(mx1, __shfl_xor_sync(0xffffffffu, mx1, 2));
        float mn0 = fmaxf(m0, mx0), mn1 = fmaxf(m1, mx1);
        float corr0 = __expf(m0 - mn0), corr1 = __expf(m1 - mn1);
        m0 = mn0; m1 = mn1;

        float ps0 = 0.f, ps1 = 0.f;
        uint32_t aPh[4][4], aPl[4][4];
        #pragma unroll
        for (int nf = 0; nf < 8; nf++) {
            float p0 = __expf(s[nf][0] - mn0);
            float p1 = __expf(s[nf][1] - mn0);
            float p2 = __expf(s[nf][2] - mn1);
            float p3 = __expf(s[nf][3] - mn1);
            ps0 += p0 + p1; ps1 += p2 + p3;
            __half h0 = __float2half_rn(p0), h1 = __float2half_rn(p1);
            __half h2 = __float2half_rn(p2), h3 = __float2half_rn(p3);
            __half e0 = __float2half_rn(p0 - __half2float(h0));
            __half e1 = __float2half_rn(p1 - __half2float(h1));
            __half e2 = __float2half_rn(p2 - __half2float(h2));
            __half e3 = __float2half_rn(p3 - __half2float(h3));
            int kf = nf >> 1, hi = nf & 1;
            half2 hh01 = __halves2half2(h0, h1), hh23 = __halves2half2(h2, h3);
            half2 ll01 = __halves2half2(e0, e1), ll23 = __halves2half2(e2, e3);
            aPh[kf][hi * 2]     = *(uint32_t*)&hh01;
            aPh[kf][hi * 2 + 1] = *(uint32_t*)&hh23;
            aPl[kf][hi * 2]     = *(uint32_t*)&ll01;
            aPl[kf][hi * 2 + 1] = *(uint32_t*)&ll23;
        }
        ps0 += __shfl_xor_sync(0xffffffffu, ps0, 1);
        ps0 += __shfl_xor_sync(0xffffffffu, ps0, 2);
        ps1 += __shfl_xor_sync(0xffffffffu, ps1, 1);
        ps1 += __shfl_xor_sync(0xffffffffu, ps1, 2);
        l0 = l0 * corr0 + ps0;
        l1 = l1 * corr1 + ps1;
        #pragma unroll
        for (int nf = 0; nf < 8; nf++) {
            o[nf][0] *= corr0; o[nf][1] *= corr0;
            o[nf][2] *= corr1; o[nf][3] *= corr1;
        }

        // O += P V split precision
        #pragma unroll
        for (int kf = 0; kf < 4; kf++) {
            #pragma unroll
            for (int np = 0; np < 4; np++) {
                int kr = kf * 16 + (lane & 7) + ((lane >> 3) & 1) * 8;
                int c = np * 16 + ((lane >> 4) & 1) * 8;
                uint32_t bVh[4], bVl[4];
                ldsm4t(bVh, &Vsh[kr * STR + c]);
                ldsm4t(bVl, &Vsl[kr * STR + c]);
                mma_f16(o[np * 2],     aPh[kf], &bVh[0]);
                mma_f16(o[np * 2 + 1], aPh[kf], &bVh[2]);
                mma_f16(o[np * 2],     aPh[kf], &bVl[0]);
                mma_f16(o[np * 2 + 1], aPh[kf], &bVl[2]);
                mma_f16(o[np * 2],     aPl[kf], &bVh[0]);
                mma_f16(o[np * 2 + 1], aPl[kf], &bVh[2]);
            }
        }
        __syncthreads();   // readers done before this buffer is refilled next iter
    }

    float inv0 = 1.0f / l0, inv1 = 1.0f / l1;
    int row0 = b * 2048 + qb * 64 + w * 16 + grp;
    #pragma unroll
    for (int nf = 0; nf < 8; nf++) {
        int col = h * 64 + nf * 8 + 2 * q;
        *(float2*)(Oout + (size_t)row0 * 1024 + col) = make_float2(o[nf][0] * inv0, o[nf][1] * inv0);
        *(float2*)(Oout + (size_t)(row0 + 8) * 1024 + col) = make_float2(o[nf][2] * inv1, o[nf][3] * inv1);
    }
}

// ---------------- single-input act quant (attention output) ----------------
__global__ __launch_bounds__(256) void act_quant_i8(const float* __restrict__ in,
                                                    int8_t* __restrict__ out,
                                                    float* __restrict__ rowscale)
{
    int row = blockIdx.x;
    int t = threadIdx.x;
    const float4* ri = (const float4*)(in + (size_t)row * 1024);
    float4 v = ri[t];
    float am = fmaxf(fmaxf(fabsf(v.x), fabsf(v.y)), fmaxf(fabsf(v.z), fabsf(v.w)));
    #pragma unroll
    for (int o = 16; o > 0; o >>= 1) am = fmaxf(am, __shfl_xor_sync(0xffffffffu, am, o));
    __shared__ float wm[8];
    if ((t & 31) == 0) wm[t >> 5] = am;
    __syncthreads();
    am = wm[0];
    #pragma unroll
    for (int i = 1; i < 8; i++) am = fmaxf(am, wm[i]);
    float amax = fmaxf(am, EPSF);
    float scale = 127.0f / amax;
    char4 o4;
    o4.x = (char)fminf(fmaxf(rintf(v.x * scale), -128.f), 127.f);
    o4.y = (char)fminf(fmaxf(rintf(v.y * scale), -128.f), 127.f);
    o4.z = (char)fminf(fmaxf(rintf(v.z * scale), -128.f), 127.f);
    o4.w = (char)fminf(fmaxf(rintf(v.w * scale), -128.f), 127.f);
    *(char4*)(out + (size_t)row * 1024 + t * 4) = o4;
    if (t == 0) rowscale[row] = amax * (1.0f / 127.0f);
}

// ---------------- launch ----------------
extern "C" void kernel_launch(void* const* d_in, const int* in_sizes, int n_in,
                              void* d_out, int out_size)
{
    (void)in_sizes; (void)n_in; (void)out_size;
    const float* x   = (const float*)d_in[0];
    const float* ctx = (const float*)d_in[1];
    const float* wq  = (const float*)d_in[2];
    const float* wk  = (const float*)d_in[3];
    const float* wv  = (const float*)d_in[4];
    const float* wo  = (const float*)d_in[5];
    float* out = (float*)d_out;

    int8_t *xq, *cq, *aq, *wt;
    float *xs, *cs, *as, *attn;
    __half *qh, *ql, *kh, *kl, *vh, *vl;
    cudaGetSymbolAddress((void**)&xq, g_xq);
    cudaGetSymbolAddress((void**)&cq, g_cq);
    cudaGetSymbolAddress((void**)&aq, g_aq);
    cudaGetSymbolAddress((void**)&wt, g_wt);
    cudaGetSymbolAddress((void**)&xs, g_xscale);
    cudaGetSymbolAddress((void**)&cs, g_cscale);
    cudaGetSymbolAddress((void**)&as, g_ascale);
    cudaGetSymbolAddress((void**)&qh, g_qh);
    cudaGetSymbolAddress((void**)&ql, g_ql);
    cudaGetSymbolAddress((void**)&kh, g_kh);
    cudaGetSymbolAddress((void**)&kl, g_kl);
    cudaGetSymbolAddress((void**)&vh, g_vh);
    cudaGetSymbolAddress((void**)&vl, g_vl);
    cudaGetSymbolAddress((void**)&attn, g_attn);

    // opt-in dynamic smem (host-side attribute set; idempotent, capture-safe)
    cudaFuncSetAttribute(gemm_proj, cudaFuncAttributeMaxDynamicSharedMemorySize, 81920);
    cudaFuncSetAttribute(gemm_out,  cudaFuncAttributeMaxDynamicSharedMemorySize, 81920);
    cudaFuncSetAttribute(attn_kernel, cudaFuncAttributeMaxDynamicSharedMemorySize, 73728);

    // weight quantization (ternary int8); scale computation fused into wquant
    wsum_kernel<<<dim3(64, 4), 256>>>(wq, wk, wv, wo);
    wquant_kernel<<<dim3(1024, 4), 256>>>(wq, wk, wv, wo);

    // activation quantization (x and ctx fused)
    act_quant2_i8<<<dim3(4096, 2), 256>>>(x, ctx, xq, cq, xs, cs);

    // fused Q/K/V projections (int8 IMMA, 4-stage pipeline); Q pre-scaled by 0.125
    gemm_proj<<<dim3(8, 32, 3), 256, 81920>>>(xq, cq, xs, cs, wt, qh, ql, kh, kl, vh, vl);

    // attention (HMMA flash, split-precision QK^T and P.V, double-buffered K/V)
    attn_kernel<<<dim3(32, 16, 2), 128, 73728>>>(qh, ql, kh, kl, vh, vl, attn);

    // output projection
    act_quant_i8<<<4096, 256>>>(attn, aq, as);
    gemm_out<<<dim3(8, 32), 256, 81920>>>(aq, as, wt, out);
}

// round 15
// speedup vs baseline: 1.1061x; 1.0253x over previous
#include <cuda_runtime.h>
#include <cuda_fp16.h>
#include <math.h>
#include <stdint.h>

#define EPSF 1e-5f

// ---------------- scratch ----------------
__device__ int8_t g_xq[4194304];     // quantized x int8 [4096,1024]
__device__ int8_t g_cq[4194304];     // quantized context int8
__device__ int8_t g_aq[4194304];     // quantized attn-out int8
__device__ int8_t g_wt[4][1048576];  // ternary weights int8 (q,k,v,o)
__device__ float  g_xscale[4096];
__device__ float  g_cscale[4096];
__device__ float  g_ascale[4096];
__device__ __half g_qh[4194304];     // Q hi fp16 (pre-scaled by 0.125*log2e)
__device__ __half g_ql[4194304];     // Q lo fp16 (residual)
__device__ __half g_kh[4194304];     // K hi
__device__ __half g_kl[4194304];     // K lo
__device__ __half g_vh[4194304];     // V hi
__device__ __half g_vl[4194304];     // V lo
__device__ float  g_attn[4194304];   // attention output fp32
__device__ double g_wpart[256];
__device__ float  g_wcm[4];
__device__ float  g_wscale[4];

// ---------------- weight |w| sum (double accumulation, deterministic) ----------------
__global__ __launch_bounds__(256) void wsum_kernel(const float* __restrict__ w0,
                                                   const float* __restrict__ w1,
                                                   const float* __restrict__ w2,
                                                   const float* __restrict__ w3)
{
    const float* w = (blockIdx.y == 0) ? w0 : (blockIdx.y == 1) ? w1 : (blockIdx.y == 2) ? w2 : w3;
    int base = blockIdx.x * 16384;
    int t = threadIdx.x;
    double s = 0.0;
    #pragma unroll
    for (int i = 0; i < 16; i++) {
        float4 v = *(const float4*)(w + base + i * 1024 + t * 4);
        s += (double)fabsf(v.x) + (double)fabsf(v.y) + (double)fabsf(v.z) + (double)fabsf(v.w);
    }
    #pragma unroll
    for (int o = 16; o > 0; o >>= 1) s += __shfl_down_sync(0xffffffffu, s, o);
    __shared__ double ws[8];
    if ((t & 31) == 0) ws[t >> 5] = s;
    __syncthreads();
    if (t == 0) {
        double tot = 0.0;
        #pragma unroll
        for (int i = 0; i < 8; i++) tot += ws[i];
        g_wpart[blockIdx.y * 64 + blockIdx.x] = tot;
    }
}

// wquant with fused scale computation (each block recomputes the deterministic mean)
__global__ __launch_bounds__(256) void wquant_kernel(const float* __restrict__ w0,
                                                     const float* __restrict__ w1,
                                                     const float* __restrict__ w2,
                                                     const float* __restrict__ w3)
{
    int m = blockIdx.y;
    const float* w = (m == 0) ? w0 : (m == 1) ? w1 : (m == 2) ? w2 : w3;
    __shared__ float sh_s;
    if (threadIdx.x == 0) {
        double tot = 0.0;
        #pragma unroll 8
        for (int i = 0; i < 64; i++) tot += g_wpart[m * 64 + i];
        float mean = (float)(tot / 1048576.0);
        float cm = fmaxf(mean, EPSF);
        sh_s = 1.0f / cm;
        if (blockIdx.x == 0) {          // publish for GEMM epilogues (deterministic value)
            g_wcm[m] = cm;
            g_wscale[m] = 1.0f / cm;
        }
    }
    __syncthreads();
    float s = sh_s;
    int idx = (blockIdx.x * 256 + threadIdx.x) * 4;
    float4 v = *(const float4*)(w + idx);
    char4 o;
    o.x = (char)fminf(fmaxf(rintf(v.x * s), -1.f), 1.f);
    o.y = (char)fminf(fmaxf(rintf(v.y * s), -1.f), 1.f);
    o.z = (char)fminf(fmaxf(rintf(v.z * s), -1.f), 1.f);
    o.w = (char)fminf(fmaxf(rintf(v.w * s), -1.f), 1.f);
    *(char4*)(g_wt[m] + idx) = o;
}

// ---------------- per-token int8 absmax quant (fused x+ctx via grid.y) ----------------
__global__ __launch_bounds__(256) void act_quant2_i8(const float* __restrict__ in0,
                                                     const float* __restrict__ in1,
                                                     int8_t* __restrict__ out0,
                                                     int8_t* __restrict__ out1,
                                                     float* __restrict__ rs0,
                                                     float* __restrict__ rs1)
{
    const float* in = blockIdx.y ? in1 : in0;
    int8_t* out = blockIdx.y ? out1 : out0;
    float* rowscale = blockIdx.y ? rs1 : rs0;
    int row = blockIdx.x;
    int t = threadIdx.x;
    const float4* ri = (const float4*)(in + (size_t)row * 1024);
    float4 v = ri[t];
    float am = fmaxf(fmaxf(fabsf(v.x), fabsf(v.y)), fmaxf(fabsf(v.z), fabsf(v.w)));
    #pragma unroll
    for (int o = 16; o > 0; o >>= 1) am = fmaxf(am, __shfl_xor_sync(0xffffffffu, am, o));
    __shared__ float wm[8];
    if ((t & 31) == 0) wm[t >> 5] = am;
    __syncthreads();
    am = wm[0];
    #pragma unroll
    for (int i = 1; i < 8; i++) am = fmaxf(am, wm[i]);
    float amax = fmaxf(am, EPSF);
    float scale = 127.0f / amax;
    char4 o4;
    o4.x = (char)fminf(fmaxf(rintf(v.x * scale), -128.f), 127.f);
    o4.y = (char)fminf(fmaxf(rintf(v.y * scale), -128.f), 127.f);
    o4.z = (char)fminf(fmaxf(rintf(v.z * scale), -128.f), 127.f);
    o4.w = (char)fminf(fmaxf(rintf(v.w * scale), -128.f), 127.f);
    *(char4*)(out + (size_t)row * 1024 + t * 4) = o4;
    if (t == 0) rowscale[row] = amax * (1.0f / 127.0f);
}

// ---------------- int8 tensor-core GEMM core (4-stage cp.async, single sync/iter) ----------------
__device__ __forceinline__ void mma_s8(int* c, const uint32_t* a, const uint32_t* b)
{
    asm volatile(
        "mma.sync.aligned.m16n8k32.row.col.s32.s8.s8.s32 "
        "{%0,%1,%2,%3}, {%4,%5,%6,%7}, {%8,%9}, {%0,%1,%2,%3};"
        : "+r"(c[0]), "+r"(c[1]), "+r"(c[2]), "+r"(c[3])
        : "r"(a[0]), "r"(a[1]), "r"(a[2]), "r"(a[3]), "r"(b[0]), "r"(b[1]));
}

// OUT_MODE: 0 = float, 2 = half hi/lo split.  smem: 4 stages x 20480 B.
template <int OUT_MODE>
__device__ __forceinline__ void gemm_body(int8_t* gsm,
                                          const int8_t* __restrict__ A,
                                          const int8_t* __restrict__ Bm,
                                          const float* __restrict__ ascale,
                                          float cmm,
                                          void* __restrict__ Cout,
                                          void* __restrict__ Cout2)
{
    int tid = threadIdx.x;
    int w = tid >> 5, lane = tid & 31;
    int grp = lane >> 2, q = lane & 3;
    int warpM = w >> 1, warpN = w & 1;
    int mBase = blockIdx.y * 128, nBase = blockIdx.x * 128;

    const int8_t* Ag = A + (size_t)mBase * 1024;
    const int8_t* Bg = Bm + (size_t)nBase * 1024;

    int acc[2][8][4];
    #pragma unroll
    for (int mf = 0; mf < 2; mf++)
        #pragma unroll
        for (int nf = 0; nf < 8; nf++)
            #pragma unroll
            for (int i = 0; i < 4; i++) acc[mf][nf][i] = 0;

    auto issue_stage = [&](int s) {
        if (s < 16) {
            int k0 = s * 64;
            int8_t* dst = gsm + (s & 3) * 20480;
            #pragma unroll
            for (int j = 0; j < 2; j++) {
                int idx = tid + j * 256;
                int row = idx >> 2, seg = idx & 3;
                uint32_t sa = (uint32_t)__cvta_generic_to_shared(dst + row * 80 + seg * 16);
                const int8_t* ga = Ag + (size_t)row * 1024 + k0 + seg * 16;
                asm volatile("cp.async.cg.shared.global [%0], [%1], 16;" :: "r"(sa), "l"(ga));
                uint32_t sb = (uint32_t)__cvta_generic_to_shared(dst + 10240 + row * 80 + seg * 16);
                const int8_t* gb = Bg + (size_t)row * 1024 + k0 + seg * 16;
                asm volatile("cp.async.cg.shared.global [%0], [%1], 16;" :: "r"(sb), "l"(gb));
            }
        }
        asm volatile("cp.async.commit_group;");   // always commit (possibly empty, keeps count exact)
    };

    issue_stage(0);
    issue_stage(1);
    issue_stage(2);

    for (int s = 0; s < 16; s++) {
        // stage s complete when <=2 newer groups outstanding (groups committed in order)
        asm volatile("cp.async.wait_group 2;");
        __syncthreads();             // also proves all warps done reading stage (s+3)&3's buffer
        issue_stage(s + 3);          // safe: overwrites buffer last read at iter s-1

        const int8_t* As = gsm + (s & 3) * 20480;
        const int8_t* Bs = As + 10240;
        #pragma unroll
        for (int ks = 0; ks < 2; ks++) {
            int koff = ks * 32;
            uint32_t afr[2][4];
            #pragma unroll
            for (int mf = 0; mf < 2; mf++) {
                int rowb = warpM * 32 + mf * 16 + grp;
                const int8_t* p = As + rowb * 80 + koff + 4 * q;
                afr[mf][0] = *(const uint32_t*)p;
                afr[mf][1] = *(const uint32_t*)(p + 8 * 80);
                afr[mf][2] = *(const uint32_t*)(p + 16);
                afr[mf][3] = *(const uint32_t*)(p + 8 * 80 + 16);
            }
            #pragma unroll
            for (int nf = 0; nf < 8; nf++) {
                int nb = warpN * 64 + nf * 8 + grp;
                const int8_t* p = Bs + nb * 80 + koff + 4 * q;
                uint32_t bfr[2];
                bfr[0] = *(const uint32_t*)p;
                bfr[1] = *(const uint32_t*)(p + 16);
                mma_s8(acc[0][nf], afr[0], bfr);
                mma_s8(acc[1][nf], afr[1], bfr);
            }
        }
        // no bottom barrier: next iter's top sync orders buffer reuse
    }

    // dequant epilogue: val = s32 * cm * (amax_row/127) * mult (exact in fp32)
    #pragma unroll
    for (int mf = 0; mf < 2; mf++) {
        int row = mBase + warpM * 32 + mf * 16 + grp;
        float f0 = cmm * ascale[row];
        float f1 = cmm * ascale[row + 8];
        #pragma unroll
        for (int nf = 0; nf < 8; nf++) {
            int col = nBase + warpN * 64 + nf * 8 + 2 * q;
            float v00 = (float)acc[mf][nf][0] * f0, v01 = (float)acc[mf][nf][1] * f0;
            float v10 = (float)acc[mf][nf][2] * f1, v11 = (float)acc[mf][nf][3] * f1;
            if (OUT_MODE == 0) {
                float* O = (float*)Cout;
                *(float2*)(O + (size_t)row * 1024 + col) = make_float2(v00, v01);
                *(float2*)(O + (size_t)(row + 8) * 1024 + col) = make_float2(v10, v11);
            } else {
                __half* Oh = (__half*)Cout;
                __half* Ol = (__half*)Cout2;
                __half h00 = __float2half_rn(v00), h01 = __float2half_rn(v01);
                __half h10 = __float2half_rn(v10), h11 = __float2half_rn(v11);
                *(half2*)(Oh + (size_t)row * 1024 + col) = __halves2half2(h00, h01);
                *(half2*)(Oh + (size_t)(row + 8) * 1024 + col) = __halves2half2(h10, h11);
                __half l00 = __float2half_rn(v00 - __half2float(h00));
                __half l01 = __float2half_rn(v01 - __half2float(h01));
                __half l10 = __float2half_rn(v10 - __half2float(h10));
                __half l11 = __float2half_rn(v11 - __half2float(h11));
                *(half2*)(Ol + (size_t)row * 1024 + col) = __halves2half2(l00, l01);
                *(half2*)(Ol + (size_t)(row + 8) * 1024 + col) = __halves2half2(l10, l11);
            }
        }
    }
}

// fused Q/K/V projection: grid (8, 32, 3)
__global__ __launch_bounds__(256) void gemm_proj(const int8_t* __restrict__ xq,
                                                 const int8_t* __restrict__ cq,
                                                 const float* __restrict__ xs,
                                                 const float* __restrict__ cs,
                                                 const int8_t* __restrict__ wt,
                                                 __half* qh, __half* ql,
                                                 __half* kh, __half* kl,
                                                 __half* vh, __half* vl)
{
    extern __shared__ int8_t gsm[];
    int z = blockIdx.z;
    const int8_t* A = (z == 0) ? xq : cq;
    const float* as_ = (z == 0) ? xs : cs;
    const int8_t* B = wt + (size_t)z * 1048576;
    void* o1 = (z == 0) ? (void*)qh : (z == 1) ? (void*)kh : (void*)vh;
    void* o2 = (z == 0) ? (void*)ql : (z == 1) ? (void*)kl : (void*)vl;
    // Q scale folds softmax 1/8 AND log2(e) so attention can use exp2f
    float cmm = g_wcm[z] * ((z == 0) ? 0.125f * 1.4426950408889634f : 1.0f);
    gemm_body<2>(gsm, A, B, as_, cmm, o1, o2);
}

// output projection: grid (8, 32)
__global__ __launch_bounds__(256) void gemm_out(const int8_t* __restrict__ aq,
                                                const float* __restrict__ as_,
                                                const int8_t* __restrict__ wt,
                                                float* __restrict__ out)
{
    extern __shared__ int8_t gsm[];
    gemm_body<0>(gsm, aq, wt + 3145728, as_, g_wcm[3], out, nullptr);
}

// ---------------- flash attention, split-fp16 hi/lo, double-buffered K/V ----------------
__device__ __forceinline__ void mma_f16(float* c, const uint32_t* a, const uint32_t* b)
{
    asm volatile(
        "mma.sync.aligned.m16n8k16.row.col.f32.f16.f16.f32 "
        "{%0,%1,%2,%3}, {%4,%5,%6,%7}, {%8,%9}, {%0,%1,%2,%3};"
        : "+f"(c[0]), "+f"(c[1]), "+f"(c[2]), "+f"(c[3])
        : "r"(a[0]), "r"(a[1]), "r"(a[2]), "r"(a[3]), "r"(b[0]), "r"(b[1]));
}

__device__ __forceinline__ void ldsm4(uint32_t* r, const void* p)
{
    uint32_t a = (uint32_t)__cvta_generic_to_shared(p);
    asm volatile("ldmatrix.sync.aligned.m8n8.x4.shared.b16 {%0,%1,%2,%3}, [%4];"
                 : "=r"(r[0]), "=r"(r[1]), "=r"(r[2]), "=r"(r[3]) : "r"(a));
}

__device__ __forceinline__ void ldsm4t(uint32_t* r, const void* p)
{
    uint32_t a = (uint32_t)__cvta_generic_to_shared(p);
    asm volatile("ldmatrix.sync.aligned.m8n8.x4.trans.shared.b16 {%0,%1,%2,%3}, [%4];"
                 : "=r"(r[0]), "=r"(r[1]), "=r"(r[2]), "=r"(r[3]) : "r"(a));
}

// grid (32 qblocks, 16 heads, 2 batch), 128 threads (4 warps).
// dynamic smem: 2 stages x 4 buffers (Ksh,Ksl,Vsh,Vsl) x 64x72 halfs = 73728 B; 3 blocks/SM.
// Scores are in log2 domain (Q pre-scaled by 0.125*log2e) -> exp2f softmax.
__global__ __launch_bounds__(128, 3) void attn_kernel(const __half* __restrict__ Qh,
                                                      const __half* __restrict__ Ql,
                                                      const __half* __restrict__ Kh,
                                                      const __half* __restrict__ Kl,
                                                      const __half* __restrict__ Vh,
                                                      const __half* __restrict__ Vl,
                                                      float* __restrict__ Oout)
{
    const int STR = 72;
    const int BUF = 64 * STR;            // 4608 halfs = 9216 bytes
    extern __shared__ __half smema[];    // [2][4][BUF]

    int b = blockIdx.z, h = blockIdx.y, qb = blockIdx.x;
    int tid = threadIdx.x;
    int w = tid >> 5, lane = tid & 31;
    int grp = lane >> 2, q = lane & 3;

    size_t qoff = (size_t)(b * 2048 + qb * 64) * 1024 + h * 64;
    size_t koff = (size_t)b * 2048 * 1024 + h * 64;

    // ---- stage Q hi/lo through smem (before cp.async pipeline touches it) ----
    uint32_t aQh[4][4], aQl[4][4];
    {
        __half* Qs = smema;
        #pragma unroll
        for (int j = 0; j < 4; j++) {
            int idx = tid + j * 128;
            int row = idx >> 3, seg = idx & 7;
            *(int4*)&Qs[row * STR + seg * 8] = *(const int4*)(Qh + qoff + (size_t)row * 1024 + seg * 8);
        }
        __syncthreads();
        #pragma unroll
        for (int kf = 0; kf < 4; kf++) {
            int r = w * 16 + (lane & 15);
            int c = kf * 16 + ((lane >> 4) << 3);
            ldsm4(aQh[kf], &Qs[r * STR + c]);
        }
        __syncthreads();
        #pragma unroll
        for (int j = 0; j < 4; j++) {
            int idx = tid + j * 128;
            int row = idx >> 3, seg = idx & 7;
            *(int4*)&Qs[row * STR + seg * 8] = *(const int4*)(Ql + qoff + (size_t)row * 1024 + seg * 8);
        }
        __syncthreads();
        #pragma unroll
        for (int kf = 0; kf < 4; kf++) {
            int r = w * 16 + (lane & 15);
            int c = kf * 16 + ((lane >> 4) << 3);
            ldsm4(aQl[kf], &Qs[r * STR + c]);
        }
        __syncthreads();   // Q frags in regs; smem free for the pipeline
    }

    // K/V prefetch: stage st holds Ksh|Ksl|Vsh|Vsl each BUF halfs
    auto issue_kv = [&](int s, int st) {
        int j0 = s * 64;
        __half* base = smema + st * 4 * BUF;
        #pragma unroll
        for (int j = 0; j < 4; j++) {
            int idx = tid + j * 128;
            int row = idx >> 3, seg = idx & 7;
            size_t g = koff + (size_t)(j0 + row) * 1024 + seg * 8;
            uint32_t d = (uint32_t)__cvta_generic_to_shared(base + row * STR + seg * 8);
            asm volatile("cp.async.cg.shared.global [%0], [%1], 16;" :: "r"(d), "l"(Kh + g));
            asm volatile("cp.async.cg.shared.global [%0], [%1], 16;" :: "r"(d + 9216u), "l"(Kl + g));
            asm volatile("cp.async.cg.shared.global [%0], [%1], 16;" :: "r"(d + 18432u), "l"(Vh + g));
            asm volatile("cp.async.cg.shared.global [%0], [%1], 16;" :: "r"(d + 27648u), "l"(Vl + g));
        }
        asm volatile("cp.async.commit_group;");
    };

    issue_kv(0, 0);

    float m0 = -1e30f, m1 = -1e30f, l0 = 0.f, l1 = 0.f;
    float o[8][4];
    #pragma unroll
    for (int nf = 0; nf < 8; nf++)
        #pragma unroll
        for (int i = 0; i < 4; i++) o[nf][i] = 0.f;

    for (int t = 0; t < 32; t++) {
        int buf = t & 1;
        asm volatile("cp.async.wait_group 0;");   // tile t's data resident
        __syncthreads();                           // all warps done with compute(t-1) too
        if (t < 31) issue_kv(t + 1, buf ^ 1);      // safe: buf^1 last read at t-1 (barrier above)

        const __half* Ksh = smema + buf * 4 * BUF;
        const __half* Ksl = Ksh + BUF;
        const __half* Vsh = Ksh + 2 * BUF;
        const __half* Vsl = Ksh + 3 * BUF;

        // S = Q K^T split precision (16 rows x 64 keys per warp), log2 domain
        float s[8][4];
        #pragma unroll
        for (int nf = 0; nf < 8; nf++)
            #pragma unroll
            for (int i = 0; i < 4; i++) s[nf][i] = 0.f;

        #pragma unroll
        for (int kf = 0; kf < 4; kf++) {
            #pragma unroll
            for (int np = 0; np < 4; np++) {
                int n = np * 16 + (lane & 7) + ((lane >> 4) & 1) * 8;
                int c = kf * 16 + ((lane >> 3) & 1) * 8;
                uint32_t bKh[4], bKl[4];
                ldsm4(bKh, &Ksh[n * STR + c]);
                ldsm4(bKl, &Ksl[n * STR + c]);
                mma_f16(s[np * 2],     aQh[kf], &bKh[0]);
                mma_f16(s[np * 2 + 1], aQh[kf], &bKh[2]);
                mma_f16(s[np * 2],     aQh[kf], &bKl[0]);
                mma_f16(s[np * 2 + 1], aQh[kf], &bKl[2]);
                mma_f16(s[np * 2],     aQl[kf], &bKh[0]);
                mma_f16(s[np * 2 + 1], aQl[kf], &bKh[2]);
            }
        }

        // online softmax in log2 domain (rows grp, grp+8 of this warp's 16)
        float mx0 = -1e30f, mx1 = -1e30f;
        #pragma unroll
        for (int nf = 0; nf < 8; nf++) {
            mx0 = fmaxf(mx0, fmaxf(s[nf][0], s[nf][1]));
            mx1 = fmaxf(mx1, fmaxf(s[nf][2], s[nf][3]));
        }
        mx0 = fmaxf(mx0, __shfl_xor_sync(0xffffffffu, mx0, 1));
        mx0 = fmaxf(mx0, __shfl_xor_sync(0xffffffffu, mx0, 2));
        mx1 = fmaxf(mx1, __shfl_xor_sync(0xffffffffu, mx1, 1));
        mx1 = fmaxf(mx1, __shfl_xor_sync(0xffffffffu, mx1, 2));
        float mn0 = fmaxf(m0, mx0), mn1 = fmaxf(m1, mx1);
        float corr0 = exp2f(m0 - mn0), corr1 = exp2f(m1 - mn1);
        m0 = mn0; m1 = mn1;

        float ps0 = 0.f, ps1 = 0.f;
        uint32_t aPh[4][4], aPl[4][4];
        #pragma unroll
        for (int nf = 0; nf < 8; nf++) {
            float p0 = exp2f(s[nf][0] - mn0);
            float p1 = exp2f(s[nf][1] - mn0);
            float p2 = exp2f(s[nf][2] - mn1);
            float p3 = exp2f(s[nf][3] - mn1);
            ps0 += p0 + p1; ps1 += p2 + p3;
            __half h0 = __float2half_rn(p0), h1 = __float2half_rn(p1);
            __half h2 = __float2half_rn(p2), h3 = __float2half_rn(p3);
            __half e0 = __float2half_rn(p0 - __half2float(h0));
            __half e1 = __float2half_rn(p1 - __half2float(h1));
            __half e2 = __float2half_rn(p2 - __half2float(h2));
            __half e3 = __float2half_rn(p3 - __half2float(h3));
            int kf = nf >> 1, hi = nf & 1;
            half2 hh01 = __halves2half2(h0, h1), hh23 = __halves2half2(h2, h3);
            half2 ll01 = __halves2half2(e0, e1), ll23 = __halves2half2(e2, e3);
            aPh[kf][hi * 2]     = *(uint32_t*)&hh01;
            aPh[kf][hi * 2 + 1] = *(uint32_t*)&hh23;
            aPl[kf][hi * 2]     = *(uint32_t*)&ll01;
            aPl[kf][hi * 2 + 1] = *(uint32_t*)&ll23;
        }
        ps0 += __shfl_xor_sync(0xffffffffu, ps0, 1);
        ps0 += __shfl_xor_sync(0xffffffffu, ps0, 2);
        ps1 += __shfl_xor_sync(0xffffffffu, ps1, 1);
        ps1 += __shfl_xor_sync(0xffffffffu, ps1, 2);
        l0 = l0 * corr0 + ps0;
        l1 = l1 * corr1 + ps1;
        #pragma unroll
        for (int nf = 0; nf < 8; nf++) {
            o[nf][0] *= corr0; o[nf][1] *= corr0;
            o[nf][2] *= corr1; o[nf][3] *= corr1;
        }

        // O += P V split precision (Ph Vh + Ph Vl + Pl Vh)
        #pragma unroll
        for (int kf = 0; kf < 4; kf++) {
            #pragma unroll
            for (int np = 0; np < 4; np++) {
                int kr = kf * 16 + (lane & 7) + ((lane >> 3) & 1) * 8;
                int c = np * 16 + ((lane >> 4) & 1) * 8;
                uint32_t bVh[4], bVl[4];
                ldsm4t(bVh, &Vsh[kr * STR + c]);
                ldsm4t(bVl, &Vsl[kr * STR + c]);
                mma_f16(o[np * 2],     aPh[kf], &bVh[0]);
                mma_f16(o[np * 2 + 1], aPh[kf], &bVh[2]);
                mma_f16(o[np * 2],     aPh[kf], &bVl[0]);
                mma_f16(o[np * 2 + 1], aPh[kf], &bVl[2]);
                mma_f16(o[np * 2],     aPl[kf], &bVh[0]);
                mma_f16(o[np * 2 + 1], aPl[kf], &bVh[2]);
            }
        }
        // no bottom barrier: next iter's top sync orders buffer reuse
    }

    float inv0 = 1.0f / l0, inv1 = 1.0f / l1;
    int row0 = b * 2048 + qb * 64 + w * 16 + grp;
    #pragma unroll
    for (int nf = 0; nf < 8; nf++) {
        int col = h * 64 + nf * 8 + 2 * q;
        *(float2*)(Oout + (size_t)row0 * 1024 + col) = make_float2(o[nf][0] * inv0, o[nf][1] * inv0);
        *(float2*)(Oout + (size_t)(row0 + 8) * 1024 + col) = make_float2(o[nf][2] * inv1, o[nf][3] * inv1);
    }
}

// ---------------- single-input act quant (attention output) ----------------
__global__ __launch_bounds__(256) void act_quant_i8(const float* __restrict__ in,
                                                    int8_t* __restrict__ out,
                                                    float* __restrict__ rowscale)
{
    int row = blockIdx.x;
    int t = threadIdx.x;
    const float4* ri = (const float4*)(in + (size_t)row * 1024);
    float4 v = ri[t];
    float am = fmaxf(fmaxf(fabsf(v.x), fabsf(v.y)), fmaxf(fabsf(v.z), fabsf(v.w)));
    #pragma unroll
    for (int o = 16; o > 0; o >>= 1) am = fmaxf(am, __shfl_xor_sync(0xffffffffu, am, o));
    __shared__ float wm[8];
    if ((t & 31) == 0) wm[t >> 5] = am;
    __syncthreads();
    am = wm[0];
    #pragma unroll
    for (int i = 1; i < 8; i++) am = fmaxf(am, wm[i]);
    float amax = fmaxf(am, EPSF);
    float scale = 127.0f / amax;
    char4 o4;
    o4.x = (char)fminf(fmaxf(rintf(v.x * scale), -128.f), 127.f);
    o4.y = (char)fminf(fmaxf(rintf(v.y * scale), -128.f), 127.f);
    o4.z = (char)fminf(fmaxf(rintf(v.z * scale), -128.f), 127.f);
    o4.w = (char)fminf(fmaxf(rintf(v.w * scale), -128.f), 127.f);
    *(char4*)(out + (size_t)row * 1024 + t * 4) = o4;
    if (t == 0) rowscale[row] = amax * (1.0f / 127.0f);
}

// ---------------- launch ----------------
extern "C" void kernel_launch(void* const* d_in, const int* in_sizes, int n_in,
                              void* d_out, int out_size)
{
    (void)in_sizes; (void)n_in; (void)out_size;
    const float* x   = (const float*)d_in[0];
    const float* ctx = (const float*)d_in[1];
    const float* wq  = (const float*)d_in[2];
    const float* wk  = (const float*)d_in[3];
    const float* wv  = (const float*)d_in[4];
    const float* wo  = (const float*)d_in[5];
    float* out = (float*)d_out;

    int8_t *xq, *cq, *aq, *wt;
    float *xs, *cs, *as, *attn;
    __half *qh, *ql, *kh, *kl, *vh, *vl;
    cudaGetSymbolAddress((void**)&xq, g_xq);
    cudaGetSymbolAddress((void**)&cq, g_cq);
    cudaGetSymbolAddress((void**)&aq, g_aq);
    cudaGetSymbolAddress((void**)&wt, g_wt);
    cudaGetSymbolAddress((void**)&xs, g_xscale);
    cudaGetSymbolAddress((void**)&cs, g_cscale);
    cudaGetSymbolAddress((void**)&as, g_ascale);
    cudaGetSymbolAddress((void**)&qh, g_qh);
    cudaGetSymbolAddress((void**)&ql, g_ql);
    cudaGetSymbolAddress((void**)&kh, g_kh);
    cudaGetSymbolAddress((void**)&kl, g_kl);
    cudaGetSymbolAddress((void**)&vh, g_vh);
    cudaGetSymbolAddress((void**)&vl, g_vl);
    cudaGetSymbolAddress((void**)&attn, g_attn);

    // opt-in dynamic smem (host-side attribute set; idempotent, capture-safe)
    cudaFuncSetAttribute(gemm_proj, cudaFuncAttributeMaxDynamicSharedMemorySize, 81920);
    cudaFuncSetAttribute(gemm_out,  cudaFuncAttributeMaxDynamicSharedMemorySize, 81920);
    cudaFuncSetAttribute(attn_kernel, cudaFuncAttributeMaxDynamicSharedMemorySize, 73728);

    // weight quantization (ternary int8); scale computation fused into wquant
    wsum_kernel<<<dim3(64, 4), 256>>>(wq, wk, wv, wo);
    wquant_kernel<<<dim3(1024, 4), 256>>>(wq, wk, wv, wo);

    // activation quantization (x and ctx fused)
    act_quant2_i8<<<dim3(4096, 2), 256>>>(x, ctx, xq, cq, xs, cs);

    // fused Q/K/V projections (int8 IMMA, 4-stage pipeline); Q pre-scaled by 0.125*log2e
    gemm_proj<<<dim3(8, 32, 3), 256, 81920>>>(xq, cq, xs, cs, wt, qh, ql, kh, kl, vh, vl);

    // attention (HMMA flash, split-precision QK^T and P.V, double-buffered K/V, exp2 softmax)
    attn_kernel<<<dim3(32, 16, 2), 128, 73728>>>(qh, ql, kh, kl, vh, vl, attn);

    // output projection
    act_quant_i8<<<4096, 256>>>(attn, aq, as);
    gemm_out<<<dim3(8, 32), 256, 81920>>>(aq, as, wt, out);
}

// round 16
// speedup vs baseline: 1.1111x; 1.0045x over previous
#include <cuda_runtime.h>
#include <cuda_fp16.h>
#include <math.h>
#include <stdint.h>

#define EPSF 1e-5f

// ---------------- scratch ----------------
__device__ int8_t g_xq[4194304];     // quantized x int8 [4096,1024]
__device__ int8_t g_cq[4194304];     // quantized context int8
__device__ int8_t g_aq[4194304];     // quantized attn-out int8
__device__ int8_t g_wt[4][1048576];  // ternary weights int8 (q,k,v,o)
__device__ float  g_xscale[4096];
__device__ float  g_cscale[4096];
__device__ float  g_ascale[4096];
__device__ __half g_qh[4194304];     // Q hi fp16 (pre-scaled by 0.125*log2e)
__device__ __half g_ql[4194304];     // Q lo fp16 (residual)
__device__ __half g_kh[4194304];     // K hi
__device__ __half g_kl[4194304];     // K lo
__device__ __half g_vh[4194304];     // V hi
__device__ __half g_vl[4194304];     // V lo
__device__ float  g_attn[4194304];   // attention output fp32
__device__ double g_wpart[256];
__device__ float  g_wcm[4];
__device__ float  g_wscale[4];

// ---------------- weight |w| sum (double accumulation, deterministic) ----------------
__global__ __launch_bounds__(256) void wsum_kernel(const float* __restrict__ w0,
                                                   const float* __restrict__ w1,
                                                   const float* __restrict__ w2,
                                                   const float* __restrict__ w3)
{
    const float* w = (blockIdx.y == 0) ? w0 : (blockIdx.y == 1) ? w1 : (blockIdx.y == 2) ? w2 : w3;
    int base = blockIdx.x * 16384;
    int t = threadIdx.x;
    double s = 0.0;
    #pragma unroll
    for (int i = 0; i < 16; i++) {
        float4 v = *(const float4*)(w + base + i * 1024 + t * 4);
        s += (double)fabsf(v.x) + (double)fabsf(v.y) + (double)fabsf(v.z) + (double)fabsf(v.w);
    }
    #pragma unroll
    for (int o = 16; o > 0; o >>= 1) s += __shfl_down_sync(0xffffffffu, s, o);
    __shared__ double ws[8];
    if ((t & 31) == 0) ws[t >> 5] = s;
    __syncthreads();
    if (t == 0) {
        double tot = 0.0;
        #pragma unroll
        for (int i = 0; i < 8; i++) tot += ws[i];
        g_wpart[blockIdx.y * 64 + blockIdx.x] = tot;
    }
}

// ---------------- fused quant: activations (2 rows/block, MLP=2) + ternary weights ----------------
// grid (4096, 3):
//   y=0: x rows   [2*bx, 2*bx+1]  (bx < 2048; others exit)
//   y=1: ctx rows [2*bx, 2*bx+1]  (bx < 2048; others exit)
//   y=2: weight quant, m = bx>>10, inner block bx&1023 (uses g_wpart from wsum)
__global__ __launch_bounds__(256) void quant_fused(const float* __restrict__ x,
                                                   const float* __restrict__ ctx,
                                                   int8_t* __restrict__ xq,
                                                   int8_t* __restrict__ cq,
                                                   float* __restrict__ xs,
                                                   float* __restrict__ cs,
                                                   const float* __restrict__ w0,
                                                   const float* __restrict__ w1,
                                                   const float* __restrict__ w2,
                                                   const float* __restrict__ w3)
{
    int t = threadIdx.x;
    if (blockIdx.y == 2) {
        int m = blockIdx.x >> 10;
        int bx = blockIdx.x & 1023;
        const float* w = (m == 0) ? w0 : (m == 1) ? w1 : (m == 2) ? w2 : w3;
        __shared__ float sh_s;
        if (t == 0) {
            double tot = 0.0;
            #pragma unroll 8
            for (int i = 0; i < 64; i++) tot += g_wpart[m * 64 + i];
            float mean = (float)(tot / 1048576.0);
            float cm = fmaxf(mean, EPSF);
            sh_s = 1.0f / cm;
            if (bx == 0) {               // publish for GEMM epilogues (deterministic value)
                g_wcm[m] = cm;
                g_wscale[m] = 1.0f / cm;
            }
        }
        __syncthreads();
        float s = sh_s;
        int idx = (bx * 256 + t) * 4;
        float4 v = *(const float4*)(w + idx);
        char4 o;
        o.x = (char)fminf(fmaxf(rintf(v.x * s), -1.f), 1.f);
        o.y = (char)fminf(fmaxf(rintf(v.y * s), -1.f), 1.f);
        o.z = (char)fminf(fmaxf(rintf(v.z * s), -1.f), 1.f);
        o.w = (char)fminf(fmaxf(rintf(v.w * s), -1.f), 1.f);
        *(char4*)(g_wt[m] + idx) = o;
        return;
    }

    if (blockIdx.x >= 2048) return;
    const float* in = blockIdx.y ? ctx : x;
    int8_t* out = blockIdx.y ? cq : xq;
    float* rowscale = blockIdx.y ? cs : xs;
    int row = blockIdx.x * 2;

    const float4* r0 = (const float4*)(in + (size_t)row * 1024);
    const float4* r1 = r0 + 256;
    float4 v0 = r0[t];
    float4 v1 = r1[t];
    float a0 = fmaxf(fmaxf(fabsf(v0.x), fabsf(v0.y)), fmaxf(fabsf(v0.z), fabsf(v0.w)));
    float a1 = fmaxf(fmaxf(fabsf(v1.x), fabsf(v1.y)), fmaxf(fabsf(v1.z), fabsf(v1.w)));
    #pragma unroll
    for (int o = 16; o > 0; o >>= 1) {
        a0 = fmaxf(a0, __shfl_xor_sync(0xffffffffu, a0, o));
        a1 = fmaxf(a1, __shfl_xor_sync(0xffffffffu, a1, o));
    }
    __shared__ float wm[2][8];
    if ((t & 31) == 0) { wm[0][t >> 5] = a0; wm[1][t >> 5] = a1; }
    __syncthreads();
    a0 = wm[0][0]; a1 = wm[1][0];
    #pragma unroll
    for (int i = 1; i < 8; i++) { a0 = fmaxf(a0, wm[0][i]); a1 = fmaxf(a1, wm[1][i]); }
    float amax0 = fmaxf(a0, EPSF), amax1 = fmaxf(a1, EPSF);
    float s0 = 127.0f / amax0, s1 = 127.0f / amax1;
    char4 o0, o1;
    o0.x = (char)fminf(fmaxf(rintf(v0.x * s0), -128.f), 127.f);
    o0.y = (char)fminf(fmaxf(rintf(v0.y * s0), -128.f), 127.f);
    o0.z = (char)fminf(fmaxf(rintf(v0.z * s0), -128.f), 127.f);
    o0.w = (char)fminf(fmaxf(rintf(v0.w * s0), -128.f), 127.f);
    o1.x = (char)fminf(fmaxf(rintf(v1.x * s1), -128.f), 127.f);
    o1.y = (char)fminf(fmaxf(rintf(v1.y * s1), -128.f), 127.f);
    o1.z = (char)fminf(fmaxf(rintf(v1.z * s1), -128.f), 127.f);
    o1.w = (char)fminf(fmaxf(rintf(v1.w * s1), -128.f), 127.f);
    *(char4*)(out + (size_t)row * 1024 + t * 4) = o0;
    *(char4*)(out + (size_t)(row + 1) * 1024 + t * 4) = o1;
    if (t == 0) {
        rowscale[row] = amax0 * (1.0f / 127.0f);
        rowscale[row + 1] = amax1 * (1.0f / 127.0f);
    }
}

// ---------------- int8 tensor-core GEMM core (4-stage cp.async, single sync/iter) ----------------
__device__ __forceinline__ void mma_s8(int* c, const uint32_t* a, const uint32_t* b)
{
    asm volatile(
        "mma.sync.aligned.m16n8k32.row.col.s32.s8.s8.s32 "
        "{%0,%1,%2,%3}, {%4,%5,%6,%7}, {%8,%9}, {%0,%1,%2,%3};"
        : "+r"(c[0]), "+r"(c[1]), "+r"(c[2]), "+r"(c[3])
        : "r"(a[0]), "r"(a[1]), "r"(a[2]), "r"(a[3]), "r"(b[0]), "r"(b[1]));
}

// OUT_MODE: 0 = float, 2 = half hi/lo split.  smem: 4 stages x 20480 B.
template <int OUT_MODE>
__device__ __forceinline__ void gemm_body(int8_t* gsm,
                                          const int8_t* __restrict__ A,
                                          const int8_t* __restrict__ Bm,
                                          const float* __restrict__ ascale,
                                          float cmm,
                                          void* __restrict__ Cout,
                                          void* __restrict__ Cout2)
{
    int tid = threadIdx.x;
    int w = tid >> 5, lane = tid & 31;
    int grp = lane >> 2, q = lane & 3;
    int warpM = w >> 1, warpN = w & 1;
    int mBase = blockIdx.y * 128, nBase = blockIdx.x * 128;

    const int8_t* Ag = A + (size_t)mBase * 1024;
    const int8_t* Bg = Bm + (size_t)nBase * 1024;

    int acc[2][8][4];
    #pragma unroll
    for (int mf = 0; mf < 2; mf++)
        #pragma unroll
        for (int nf = 0; nf < 8; nf++)
            #pragma unroll
            for (int i = 0; i < 4; i++) acc[mf][nf][i] = 0;

    auto issue_stage = [&](int s) {
        if (s < 16) {
            int k0 = s * 64;
            int8_t* dst = gsm + (s & 3) * 20480;
            #pragma unroll
            for (int j = 0; j < 2; j++) {
                int idx = tid + j * 256;
                int row = idx >> 2, seg = idx & 3;
                uint32_t sa = (uint32_t)__cvta_generic_to_shared(dst + row * 80 + seg * 16);
                const int8_t* ga = Ag + (size_t)row * 1024 + k0 + seg * 16;
                asm volatile("cp.async.cg.shared.global [%0], [%1], 16;" :: "r"(sa), "l"(ga));
                uint32_t sb = (uint32_t)__cvta_generic_to_shared(dst + 10240 + row * 80 + seg * 16);
                const int8_t* gb = Bg + (size_t)row * 1024 + k0 + seg * 16;
                asm volatile("cp.async.cg.shared.global [%0], [%1], 16;" :: "r"(sb), "l"(gb));
            }
        }
        asm volatile("cp.async.commit_group;");   // always commit (keeps group count exact)
    };

    issue_stage(0);
    issue_stage(1);
    issue_stage(2);

    for (int s = 0; s < 16; s++) {
        asm volatile("cp.async.wait_group 2;");
        __syncthreads();             // proves all warps done reading the buffer issue will overwrite
        issue_stage(s + 3);

        const int8_t* As = gsm + (s & 3) * 20480;
        const int8_t* Bs = As + 10240;
        #pragma unroll
        for (int ks = 0; ks < 2; ks++) {
            int koff = ks * 32;
            uint32_t afr[2][4];
            #pragma unroll
            for (int mf = 0; mf < 2; mf++) {
                int rowb = warpM * 32 + mf * 16 + grp;
                const int8_t* p = As + rowb * 80 + koff + 4 * q;
                afr[mf][0] = *(const uint32_t*)p;
                afr[mf][1] = *(const uint32_t*)(p + 8 * 80);
                afr[mf][2] = *(const uint32_t*)(p + 16);
                afr[mf][3] = *(const uint32_t*)(p + 8 * 80 + 16);
            }
            #pragma unroll
            for (int nf = 0; nf < 8; nf++) {
                int nb = warpN * 64 + nf * 8 + grp;
                const int8_t* p = Bs + nb * 80 + koff + 4 * q;
                uint32_t bfr[2];
                bfr[0] = *(const uint32_t*)p;
                bfr[1] = *(const uint32_t*)(p + 16);
                mma_s8(acc[0][nf], afr[0], bfr);
                mma_s8(acc[1][nf], afr[1], bfr);
            }
        }
        // no bottom barrier: next iter's top sync orders buffer reuse
    }

    // dequant epilogue: val = s32 * cm * (amax_row/127) * mult (exact in fp32)
    #pragma unroll
    for (int mf = 0; mf < 2; mf++) {
        int row = mBase + warpM * 32 + mf * 16 + grp;
        float f0 = cmm * ascale[row];
        float f1 = cmm * ascale[row + 8];
        #pragma unroll
        for (int nf = 0; nf < 8; nf++) {
            int col = nBase + warpN * 64 + nf * 8 + 2 * q;
            float v00 = (float)acc[mf][nf][0] * f0, v01 = (float)acc[mf][nf][1] * f0;
            float v10 = (float)acc[mf][nf][2] * f1, v11 = (float)acc[mf][nf][3] * f1;
            if (OUT_MODE == 0) {
                float* O = (float*)Cout;
                *(float2*)(O + (size_t)row * 1024 + col) = make_float2(v00, v01);
                *(float2*)(O + (size_t)(row + 8) * 1024 + col) = make_float2(v10, v11);
            } else {
                __half* Oh = (__half*)Cout;
                __half* Ol = (__half*)Cout2;
                __half h00 = __float2half_rn(v00), h01 = __float2half_rn(v01);
                __half h10 = __float2half_rn(v10), h11 = __float2half_rn(v11);
                *(half2*)(Oh + (size_t)row * 1024 + col) = __halves2half2(h00, h01);
                *(half2*)(Oh + (size_t)(row + 8) * 1024 + col) = __halves2half2(h10, h11);
                __half l00 = __float2half_rn(v00 - __half2float(h00));
                __half l01 = __float2half_rn(v01 - __half2float(h01));
                __half l10 = __float2half_rn(v10 - __half2float(h10));
                __half l11 = __float2half_rn(v11 - __half2float(h11));
                *(half2*)(Ol + (size_t)row * 1024 + col) = __halves2half2(l00, l01);
                *(half2*)(Ol + (size_t)(row + 8) * 1024 + col) = __halves2half2(l10, l11);
            }
        }
    }
}

// fused Q/K/V projection: grid (8, 32, 3)
__global__ __launch_bounds__(256) void gemm_proj(const int8_t* __restrict__ xq,
                                                 const int8_t* __restrict__ cq,
                                                 const float* __restrict__ xs,
                                                 const float* __restrict__ cs,
                                                 const int8_t* __restrict__ wt,
                                                 __half* qh, __half* ql,
                                                 __half* kh, __half* kl,
                                                 __half* vh, __half* vl)
{
    extern __shared__ int8_t gsm[];
    int z = blockIdx.z;
    const int8_t* A = (z == 0) ? xq : cq;
    const float* as_ = (z == 0) ? xs : cs;
    const int8_t* B = wt + (size_t)z * 1048576;
    void* o1 = (z == 0) ? (void*)qh : (z == 1) ? (void*)kh : (void*)vh;
    void* o2 = (z == 0) ? (void*)ql : (z == 1) ? (void*)kl : (void*)vl;
    // Q scale folds softmax 1/8 AND log2(e) so attention can use exp2f
    float cmm = g_wcm[z] * ((z == 0) ? 0.125f * 1.4426950408889634f : 1.0f);
    gemm_body<2>(gsm, A, B, as_, cmm, o1, o2);
}

// output projection: grid (8, 32)
__global__ __launch_bounds__(256) void gemm_out(const int8_t* __restrict__ aq,
                                                const float* __restrict__ as_,
                                                const int8_t* __restrict__ wt,
                                                float* __restrict__ out)
{
    extern __shared__ int8_t gsm[];
    gemm_body<0>(gsm, aq, wt + 3145728, as_, g_wcm[3], out, nullptr);
}

// ---------------- flash attention, split-fp16 hi/lo, double-buffered K/V ----------------
__device__ __forceinline__ void mma_f16(float* c, const uint32_t* a, const uint32_t* b)
{
    asm volatile(
        "mma.sync.aligned.m16n8k16.row.col.f32.f16.f16.f32 "
        "{%0,%1,%2,%3}, {%4,%5,%6,%7}, {%8,%9}, {%0,%1,%2,%3};"
        : "+f"(c[0]), "+f"(c[1]), "+f"(c[2]), "+f"(c[3])
        : "r"(a[0]), "r"(a[1]), "r"(a[2]), "r"(a[3]), "r"(b[0]), "r"(b[1]));
}

__device__ __forceinline__ void ldsm4(uint32_t* r, const void* p)
{
    uint32_t a = (uint32_t)__cvta_generic_to_shared(p);
    asm volatile("ldmatrix.sync.aligned.m8n8.x4.shared.b16 {%0,%1,%2,%3}, [%4];"
                 : "=r"(r[0]), "=r"(r[1]), "=r"(r[2]), "=r"(r[3]) : "r"(a));
}

__device__ __forceinline__ void ldsm4t(uint32_t* r, const void* p)
{
    uint32_t a = (uint32_t)__cvta_generic_to_shared(p);
    asm volatile("ldmatrix.sync.aligned.m8n8.x4.trans.shared.b16 {%0,%1,%2,%3}, [%4];"
                 : "=r"(r[0]), "=r"(r[1]), "=r"(r[2]), "=r"(r[3]) : "r"(a));
}

// grid (32 qblocks, 16 heads, 2 batch), 128 threads (4 warps).
// dynamic smem: 2 stages x 4 buffers (Ksh,Ksl,Vsh,Vsl) x 64x72 halfs = 73728 B; 3 blocks/SM.
// Scores in log2 domain (Q pre-scaled by 0.125*log2e) -> exp2f softmax.
__global__ __launch_bounds__(128, 3) void attn_kernel(const __half* __restrict__ Qh,
                                                      const __half* __restrict__ Ql,
                                                      const __half* __restrict__ Kh,
                                                      const __half* __restrict__ Kl,
                                                      const __half* __restrict__ Vh,
                                                      const __half* __restrict__ Vl,
                                                      float* __restrict__ Oout)
{
    const int STR = 72;
    const int BUF = 64 * STR;            // 4608 halfs = 9216 bytes
    extern __shared__ __half smema[];    // [2][4][BUF]

    int b = blockIdx.z, h = blockIdx.y, qb = blockIdx.x;
    int tid = threadIdx.x;
    int w = tid >> 5, lane = tid & 31;
    int grp = lane >> 2, q = lane & 3;

    size_t qoff = (size_t)(b * 2048 + qb * 64) * 1024 + h * 64;
    size_t koff = (size_t)b * 2048 * 1024 + h * 64;

    // ---- stage Q hi/lo through smem (before cp.async pipeline touches it) ----
    uint32_t aQh[4][4], aQl[4][4];
    {
        __half* Qs = smema;
        #pragma unroll
        for (int j = 0; j < 4; j++) {
            int idx = tid + j * 128;
            int row = idx >> 3, seg = idx & 7;
            *(int4*)&Qs[row * STR + seg * 8] = *(const int4*)(Qh + qoff + (size_t)row * 1024 + seg * 8);
        }
        __syncthreads();
        #pragma unroll
        for (int kf = 0; kf < 4; kf++) {
            int r = w * 16 + (lane & 15);
            int c = kf * 16 + ((lane >> 4) << 3);
            ldsm4(aQh[kf], &Qs[r * STR + c]);
        }
        __syncthreads();
        #pragma unroll
        for (int j = 0; j < 4; j++) {
            int idx = tid + j * 128;
            int row = idx >> 3, seg = idx & 7;
            *(int4*)&Qs[row * STR + seg * 8] = *(const int4*)(Ql + qoff + (size_t)row * 1024 + seg * 8);
        }
        __syncthreads();
        #pragma unroll
        for (int kf = 0; kf < 4; kf++) {
            int r = w * 16 + (lane & 15);
            int c = kf * 16 + ((lane >> 4) << 3);
            ldsm4(aQl[kf], &Qs[r * STR + c]);
        }
        __syncthreads();   // Q frags in regs; smem free for the pipeline
    }

    // K/V prefetch: stage st holds Ksh|Ksl|Vsh|Vsl each BUF halfs
    auto issue_kv = [&](int s, int st) {
        int j0 = s * 64;
        __half* base = smema + st * 4 * BUF;
        #pragma unroll
        for (int j = 0; j < 4; j++) {
            int idx = tid + j * 128;
            int row = idx >> 3, seg = idx & 7;
            size_t g = koff + (size_t)(j0 + row) * 1024 + seg * 8;
            uint32_t d = (uint32_t)__cvta_generic_to_shared(base + row * STR + seg * 8);
            asm volatile("cp.async.cg.shared.global [%0], [%1], 16;" :: "r"(d), "l"(Kh + g));
            asm volatile("cp.async.cg.shared.global [%0], [%1], 16;" :: "r"(d + 9216u), "l"(Kl + g));
            asm volatile("cp.async.cg.shared.global [%0], [%1], 16;" :: "r"(d + 18432u), "l"(Vh + g));
            asm volatile("cp.async.cg.shared.global [%0], [%1], 16;" :: "r"(d + 27648u), "l"(Vl + g));
        }
        asm volatile("cp.async.commit_group;");
    };

    issue_kv(0, 0);

    float m0 = -1e30f, m1 = -1e30f, l0 = 0.f, l1 = 0.f;
    float o[8][4];
    #pragma unroll
    for (int nf = 0; nf < 8; nf++)
        #pragma unroll
        for (int i = 0; i < 4; i++) o[nf][i] = 0.f;

    for (int t = 0; t < 32; t++) {
        int buf = t & 1;
        asm volatile("cp.async.wait_group 0;");   // tile t's data resident
        __syncthreads();                           // all warps done with compute(t-1) too
        if (t < 31) issue_kv(t + 1, buf ^ 1);      // safe: buf^1 last read at t-1 (barrier above)

        const __half* Ksh = smema + buf * 4 * BUF;
        const __half* Ksl = Ksh + BUF;
        const __half* Vsh = Ksh + 2 * BUF;
        const __half* Vsl = Ksh + 3 * BUF;

        // S = Q K^T split precision (16 rows x 64 keys per warp), log2 domain
        float s[8][4];
        #pragma unroll
        for (int nf = 0; nf < 8; nf++)
            #pragma unroll
            for (int i = 0; i < 4; i++) s[nf][i] = 0.f;

        #pragma unroll
        for (int kf = 0; kf < 4; kf++) {
            #pragma unroll
            for (int np = 0; np < 4; np++) {
                int n = np * 16 + (lane & 7) + ((lane >> 4) & 1) * 8;
                int c = kf * 16 + ((lane >> 3) & 1) * 8;
                uint32_t bKh[4], bKl[4];
                ldsm4(bKh, &Ksh[n * STR + c]);
                ldsm4(bKl, &Ksl[n * STR + c]);
                mma_f16(s[np * 2],     aQh[kf], &bKh[0]);
                mma_f16(s[np * 2 + 1], aQh[kf], &bKh[2]);
                mma_f16(s[np * 2],     aQh[kf], &bKl[0]);
                mma_f16(s[np * 2 + 1], aQh[kf], &bKl[2]);
                mma_f16(s[np * 2],     aQl[kf], &bKh[0]);
                mma_f16(s[np * 2 + 1], aQl[kf], &bKh[2]);
            }
        }

        // online softmax in log2 domain (rows grp, grp+8 of this warp's 16)
        float mx0 = -1e30f, mx1 = -1e30f;
        #pragma unroll
        for (int nf = 0; nf < 8; nf++) {
            mx0 = fmaxf(mx0, fmaxf(s[nf][0], s[nf][1]));
            mx1 = fmaxf(mx1, fmaxf(s[nf][2], s[nf][3]));
        }
        mx0 = fmaxf(mx0, __shfl_xor_sync(0xffffffffu, mx0, 1));
        mx0 = fmaxf(mx0, __shfl_xor_sync(0xffffffffu, mx0, 2));
        mx1 = fmaxf(mx1, __shfl_xor_sync(0xffffffffu, mx1, 1));
        mx1 = fmaxf(mx1, __shfl_xor_sync(0xffffffffu, mx1, 2));
        float mn0 = fmaxf(m0, mx0), mn1 = fmaxf(m1, mx1);
        float corr0 = exp2f(m0 - mn0), corr1 = exp2f(m1 - mn1);
        m0 = mn0; m1 = mn1;

        float ps0 = 0.f, ps1 = 0.f;
        uint32_t aPh[4][4], aPl[4][4];
        #pragma unroll
        for (int nf = 0; nf < 8; nf++) {
            float p0 = exp2f(s[nf][0] - mn0);
            float p1 = exp2f(s[nf][1] - mn0);
            float p2 = exp2f(s[nf][2] - mn1);
            float p3 = exp2f(s[nf][3] - mn1);
            ps0 += p0 + p1; ps1 += p2 + p3;
            __half h0 = __float2half_rn(p0), h1 = __float2half_rn(p1);
            __half h2 = __float2half_rn(p2), h3 = __float2half_rn(p3);
            __half e0 = __float2half_rn(p0 - __half2float(h0));
            __half e1 = __float2half_rn(p1 - __half2float(h1));
            __half e2 = __float2half_rn(p2 - __half2float(h2));
            __half e3 = __float2half_rn(p3 - __half2float(h3));
            int kf = nf >> 1, hi = nf & 1;
            half2 hh01 = __halves2half2(h0, h1), hh23 = __halves2half2(h2, h3);
            half2 ll01 = __halves2half2(e0, e1), ll23 = __halves2half2(e2, e3);
            aPh[kf][hi * 2]     = *(uint32_t*)&hh01;
            aPh[kf][hi * 2 + 1] = *(uint32_t*)&hh23;
            aPl[kf][hi * 2]     = *(uint32_t*)&ll01;
            aPl[kf][hi * 2 + 1] = *(uint32_t*)&ll23;
        }
        ps0 += __shfl_xor_sync(0xffffffffu, ps0, 1);
        ps0 += __shfl_xor_sync(0xffffffffu, ps0, 2);
        ps1 += __shfl_xor_sync(0xffffffffu, ps1, 1);
        ps1 += __shfl_xor_sync(0xffffffffu, ps1, 2);
        l0 = l0 * corr0 + ps0;
        l1 = l1 * corr1 + ps1;
        #pragma unroll
        for (int nf = 0; nf < 8; nf++) {
            o[nf][0] *= corr0; o[nf][1] *= corr0;
            o[nf][2] *= corr1; o[nf][3] *= corr1;
        }

        // O += P V split precision (Ph Vh + Ph Vl + Pl Vh)
        #pragma unroll
        for (int kf = 0; kf < 4; kf++) {
            #pragma unroll
            for (int np = 0; np < 4; np++) {
                int kr = kf * 16 + (lane & 7) + ((lane >> 3) & 1) * 8;
                int c = np * 16 + ((lane >> 4) & 1) * 8;
                uint32_t bVh[4], bVl[4];
                ldsm4t(bVh, &Vsh[kr * STR + c]);
                ldsm4t(bVl, &Vsl[kr * STR + c]);
                mma_f16(o[np * 2],     aPh[kf], &bVh[0]);
                mma_f16(o[np * 2 + 1], aPh[kf], &bVh[2]);
                mma_f16(o[np * 2],     aPh[kf], &bVl[0]);
                mma_f16(o[np * 2 + 1], aPh[kf], &bVl[2]);
                mma_f16(o[np * 2],     aPl[kf], &bVh[0]);
                mma_f16(o[np * 2 + 1], aPl[kf], &bVh[2]);
            }
        }
        // no bottom barrier: next iter's top sync orders buffer reuse
    }

    float inv0 = 1.0f / l0, inv1 = 1.0f / l1;
    int row0 = b * 2048 + qb * 64 + w * 16 + grp;
    #pragma unroll
    for (int nf = 0; nf < 8; nf++) {
        int col = h * 64 + nf * 8 + 2 * q;
        *(float2*)(Oout + (size_t)row0 * 1024 + col) = make_float2(o[nf][0] * inv0, o[nf][1] * inv0);
        *(float2*)(Oout + (size_t)(row0 + 8) * 1024 + col) = make_float2(o[nf][2] * inv1, o[nf][3] * inv1);
    }
}

// ---------------- act quant for attention output (2 rows/block, MLP=2) ----------------
__global__ __launch_bounds__(256) void act_quant_i8(const float* __restrict__ in,
                                                    int8_t* __restrict__ out,
                                                    float* __restrict__ rowscale)
{
    int t = threadIdx.x;
    int row = blockIdx.x * 2;
    const float4* r0 = (const float4*)(in + (size_t)row * 1024);
    const float4* r1 = r0 + 256;
    float4 v0 = r0[t];
    float4 v1 = r1[t];
    float a0 = fmaxf(fmaxf(fabsf(v0.x), fabsf(v0.y)), fmaxf(fabsf(v0.z), fabsf(v0.w)));
    float a1 = fmaxf(fmaxf(fabsf(v1.x), fabsf(v1.y)), fmaxf(fabsf(v1.z), fabsf(v1.w)));
    #pragma unroll
    for (int o = 16; o > 0; o >>= 1) {
        a0 = fmaxf(a0, __shfl_xor_sync(0xffffffffu, a0, o));
        a1 = fmaxf(a1, __shfl_xor_sync(0xffffffffu, a1, o));
    }
    __shared__ float wm[2][8];
    if ((t & 31) == 0) { wm[0][t >> 5] = a0; wm[1][t >> 5] = a1; }
    __syncthreads();
    a0 = wm[0][0]; a1 = wm[1][0];
    #pragma unroll
    for (int i = 1; i < 8; i++) { a0 = fmaxf(a0, wm[0][i]); a1 = fmaxf(a1, wm[1][i]); }
    float amax0 = fmaxf(a0, EPSF), amax1 = fmaxf(a1, EPSF);
    float s0 = 127.0f / amax0, s1 = 127.0f / amax1;
    char4 o0, o1;
    o0.x = (char)fminf(fmaxf(rintf(v0.x * s0), -128.f), 127.f);
    o0.y = (char)fminf(fmaxf(rintf(v0.y * s0), -128.f), 127.f);
    o0.z = (char)fminf(fmaxf(rintf(v0.z * s0), -128.f), 127.f);
    o0.w = (char)fminf(fmaxf(rintf(v0.w * s0), -128.f), 127.f);
    o1.x = (char)fminf(fmaxf(rintf(v1.x * s1), -128.f), 127.f);
    o1.y = (char)fminf(fmaxf(rintf(v1.y * s1), -128.f), 127.f);
    o1.z = (char)fminf(fmaxf(rintf(v1.z * s1), -128.f), 127.f);
    o1.w = (char)fminf(fmaxf(rintf(v1.w * s1), -128.f), 127.f);
    *(char4*)(out + (size_t)row * 1024 + t * 4) = o0;
    *(char4*)(out + (size_t)(row + 1) * 1024 + t * 4) = o1;
    if (t == 0) {
        rowscale[row] = amax0 * (1.0f / 127.0f);
        rowscale[row + 1] = amax1 * (1.0f / 127.0f);
    }
}

// ---------------- launch ----------------
extern "C" void kernel_launch(void* const* d_in, const int* in_sizes, int n_in,
                              void* d_out, int out_size)
{
    (void)in_sizes; (void)n_in; (void)out_size;
    const float* x   = (const float*)d_in[0];
    const float* ctx = (const float*)d_in[1];
    const float* wq  = (const float*)d_in[2];
    const float* wk  = (const float*)d_in[3];
    const float* wv  = (const float*)d_in[4];
    const float* wo  = (const float*)d_in[5];
    float* out = (float*)d_out;

    int8_t *xq, *cq, *aq, *wt;
    float *xs, *cs, *as, *attn;
    __half *qh, *ql, *kh, *kl, *vh, *vl;
    cudaGetSymbolAddress((void**)&xq, g_xq);
    cudaGetSymbolAddress((void**)&cq, g_cq);
    cudaGetSymbolAddress((void**)&aq, g_aq);
    cudaGetSymbolAddress((void**)&wt, g_wt);
    cudaGetSymbolAddress((void**)&xs, g_xscale);
    cudaGetSymbolAddress((void**)&cs, g_cscale);
    cudaGetSymbolAddress((void**)&as, g_ascale);
    cudaGetSymbolAddress((void**)&qh, g_qh);
    cudaGetSymbolAddress((void**)&ql, g_ql);
    cudaGetSymbolAddress((void**)&kh, g_kh);
    cudaGetSymbolAddress((void**)&kl, g_kl);
    cudaGetSymbolAddress((void**)&vh, g_vh);
    cudaGetSymbolAddress((void**)&vl, g_vl);
    cudaGetSymbolAddress((void**)&attn, g_attn);

    // opt-in dynamic smem (host-side attribute set; idempotent, capture-safe)
    cudaFuncSetAttribute(gemm_proj, cudaFuncAttributeMaxDynamicSharedMemorySize, 81920);
    cudaFuncSetAttribute(gemm_out,  cudaFuncAttributeMaxDynamicSharedMemorySize, 81920);
    cudaFuncSetAttribute(attn_kernel, cudaFuncAttributeMaxDynamicSharedMemorySize, 73728);

    // weight |w| sums (needed by quant_fused's weight slice)
    wsum_kernel<<<dim3(64, 4), 256>>>(wq, wk, wv, wo);

    // fused: activation quant (x+ctx, 2 rows/block) + ternary weight quant
    quant_fused<<<dim3(4096, 3), 256>>>(x, ctx, xq, cq, xs, cs, wq, wk, wv, wo);

    // fused Q/K/V projections (int8 IMMA, 4-stage pipeline); Q pre-scaled by 0.125*log2e
    gemm_proj<<<dim3(8, 32, 3), 256, 81920>>>(xq, cq, xs, cs, wt, qh, ql, kh, kl, vh, vl);

    // attention (HMMA flash, split-precision QK^T and P.V, double-buffered K/V, exp2 softmax)
    attn_kernel<<<dim3(32, 16, 2), 128, 73728>>>(qh, ql, kh, kl, vh, vl, attn);

    // output projection
    act_quant_i8<<<2048, 256>>>(attn, aq, as);
    gemm_out<<<dim3(8, 32), 256, 81920>>>(aq, as, wt, out);
}